// round 1
// baseline (speedup 1.0000x reference)
#include <cuda_runtime.h>
#include <math.h>

#define D 1024
#define NSEQ 2048
#define NB 2
#define NH 16
#define HC 64
#define M_TOTAL (NB * NSEQ)  // 4096

// Scratch (allocation-free rule: __device__ globals)
__device__ float g_Q[M_TOTAL * D];
__device__ float g_K[M_TOTAL * D];
__device__ float g_V[M_TOTAL * D];
__device__ float g_O[M_TOTAL * D];

// ---------------------------------------------------------------------------
// SGEMM: C[M,1024] = A[M,1024] @ B[1024,1024] (+ optional bias broadcast on N)
// 128x128 block tile, BK=16, 256 threads, 8x8 per-thread microtile.
// ---------------------------------------------------------------------------
__global__ __launch_bounds__(256) void sgemm_kernel(
    const float* __restrict__ A, const float* __restrict__ B,
    const float* __restrict__ bias, float* __restrict__ C) {
  __shared__ float As[16][128];  // transposed A tile: As[k][m]
  __shared__ float Bs[16][128];  // natural B tile:  Bs[k][n]

  const int tid = threadIdx.x;
  const int bm = blockIdx.y * 128;
  const int bn = blockIdx.x * 128;
  const int tm = (tid >> 4) << 3;  // row group * 8
  const int tn = (tid & 15) << 3;  // col group * 8

  const int a_row = tid >> 2;        // 0..63
  const int a_col = (tid & 3) << 2;  // 0,4,8,12
  const int b_row = tid >> 5;        // 0..7
  const int b_col = (tid & 31) << 2; // 0..124

  float acc[8][8];
#pragma unroll
  for (int i = 0; i < 8; i++)
#pragma unroll
    for (int j = 0; j < 8; j++) acc[i][j] = 0.f;

  for (int k0 = 0; k0 < D; k0 += 16) {
    __syncthreads();
#pragma unroll
    for (int r = 0; r < 2; r++) {
      int row = a_row + (r << 6);
      float4 v = *(const float4*)(A + (size_t)(bm + row) * D + k0 + a_col);
      As[a_col + 0][row] = v.x;
      As[a_col + 1][row] = v.y;
      As[a_col + 2][row] = v.z;
      As[a_col + 3][row] = v.w;
    }
#pragma unroll
    for (int r = 0; r < 2; r++) {
      int row = b_row + (r << 3);
      *(float4*)&Bs[row][b_col] =
          *(const float4*)(B + (size_t)(k0 + row) * D + bn + b_col);
    }
    __syncthreads();
#pragma unroll
    for (int kk = 0; kk < 16; kk++) {
      float a[8], b[8];
      float4 t;
      t = *(const float4*)&As[kk][tm];     a[0]=t.x; a[1]=t.y; a[2]=t.z; a[3]=t.w;
      t = *(const float4*)&As[kk][tm + 4]; a[4]=t.x; a[5]=t.y; a[6]=t.z; a[7]=t.w;
      t = *(const float4*)&Bs[kk][tn];     b[0]=t.x; b[1]=t.y; b[2]=t.z; b[3]=t.w;
      t = *(const float4*)&Bs[kk][tn + 4]; b[4]=t.x; b[5]=t.y; b[6]=t.z; b[7]=t.w;
#pragma unroll
      for (int i = 0; i < 8; i++)
#pragma unroll
        for (int j = 0; j < 8; j++) acc[i][j] = fmaf(a[i], b[j], acc[i][j]);
    }
  }

  float bv[8];
  if (bias) {
#pragma unroll
    for (int j = 0; j < 8; j++) bv[j] = bias[bn + tn + j];
  } else {
#pragma unroll
    for (int j = 0; j < 8; j++) bv[j] = 0.f;
  }
#pragma unroll
  for (int i = 0; i < 8; i++) {
    float4 o0 = make_float4(acc[i][0] + bv[0], acc[i][1] + bv[1],
                            acc[i][2] + bv[2], acc[i][3] + bv[3]);
    float4 o1 = make_float4(acc[i][4] + bv[4], acc[i][5] + bv[5],
                            acc[i][6] + bv[6], acc[i][7] + bv[7]);
    float* crow = C + (size_t)(bm + tm + i) * D + bn + tn;
    *(float4*)(crow) = o0;
    *(float4*)(crow + 4) = o1;
  }
}

// ---------------------------------------------------------------------------
// Flash attention, fp32. One block per (batch, head, 64-row q tile).
// 256 threads as 16x16; each thread owns a 4x4 patch of S (q x k) and of
// O (q x c). K stored c-major with XOR swizzle; P staged through the same
// smem buffer as K (union) to keep static smem at exactly 48 KB.
// mask[b,q,k] != 0  => logit = -inf (inverted-mask semantics).
// ---------------------------------------------------------------------------
__global__ __launch_bounds__(256) void attn_kernel(
    const float* __restrict__ Qg, const float* __restrict__ Kg,
    const float* __restrict__ Vg, const int* __restrict__ mask,
    float* __restrict__ Og) {
  __shared__ float Qs[64 * 64];  // [q][c]
  __shared__ float KP[64 * 64];  // phase1: Ks[c][k^swz]; phase2: Ps[q][k]
  __shared__ float Vs[64 * 64];  // [k][c]

  const int tid = threadIdx.x;
  const int qt = blockIdx.x;
  const int h  = blockIdx.y;
  const int bb = blockIdx.z;
  const int ty = tid >> 4;       // 0..15 : q group
  const int tx = tid & 15;       // 0..15 : k / c group
  const int qrow = ty << 2;
  const int kcol = tx << 2;

  const int q0 = qt * 64;
  const size_t rowbase = (size_t)bb * NSEQ;
  const int colbase = h * HC;

  // Load Q tile (natural layout)
#pragma unroll
  for (int r = 0; r < 4; r++) {
    int idx = tid + (r << 8);
    int q = idx >> 4;
    int c4 = (idx & 15) << 2;
    *(float4*)&Qs[q * 64 + c4] =
        *(const float4*)&Qg[(rowbase + q0 + q) * D + colbase + c4];
  }

  float o[4][4];
  float rmax[4], rsum[4];
#pragma unroll
  for (int i = 0; i < 4; i++) {
    rmax[i] = -1e30f;
    rsum[i] = 0.f;
#pragma unroll
    for (int j = 0; j < 4; j++) o[i][j] = 0.f;
  }

  const float scale = 0.125f;  // 1/sqrt(64)
  const float NEG_INF = __int_as_float(0xff800000);

  for (int kb = 0; kb < NSEQ; kb += 64) {
    __syncthreads();  // protect KP (read as P last iter) and Vs
    // Load K tile transposed (c-major) with XOR swizzle on k bits [4:2];
    // V tile natural.
#pragma unroll
    for (int r = 0; r < 4; r++) {
      int idx = tid + (r << 8);
      int k = idx >> 4;
      int c4 = (idx & 15) << 2;
      float4 kv = *(const float4*)&Kg[(rowbase + kb + k) * D + colbase + c4];
      int swz = ((c4 >> 2) & 7) << 2;
      int kp = k ^ swz;
      KP[(c4 + 0) * 64 + kp] = kv.x;
      KP[(c4 + 1) * 64 + kp] = kv.y;
      KP[(c4 + 2) * 64 + kp] = kv.z;
      KP[(c4 + 3) * 64 + kp] = kv.w;
      *(float4*)&Vs[k * 64 + c4] =
          *(const float4*)&Vg[(rowbase + kb + k) * D + colbase + c4];
    }
    __syncthreads();

    // S = Q @ K^T for this tile
    float s[4][4];
#pragma unroll
    for (int i = 0; i < 4; i++)
#pragma unroll
      for (int j = 0; j < 4; j++) s[i][j] = 0.f;

#pragma unroll 16
    for (int cc = 0; cc < 64; cc++) {
      int swz = ((cc >> 2) & 7) << 2;
      float4 bk = *(const float4*)&KP[cc * 64 + (kcol ^ swz)];
      float a0 = Qs[(qrow + 0) * 64 + cc];
      float a1 = Qs[(qrow + 1) * 64 + cc];
      float a2 = Qs[(qrow + 2) * 64 + cc];
      float a3 = Qs[(qrow + 3) * 64 + cc];
      s[0][0] = fmaf(a0, bk.x, s[0][0]); s[0][1] = fmaf(a0, bk.y, s[0][1]);
      s[0][2] = fmaf(a0, bk.z, s[0][2]); s[0][3] = fmaf(a0, bk.w, s[0][3]);
      s[1][0] = fmaf(a1, bk.x, s[1][0]); s[1][1] = fmaf(a1, bk.y, s[1][1]);
      s[1][2] = fmaf(a1, bk.z, s[1][2]); s[1][3] = fmaf(a1, bk.w, s[1][3]);
      s[2][0] = fmaf(a2, bk.x, s[2][0]); s[2][1] = fmaf(a2, bk.y, s[2][1]);
      s[2][2] = fmaf(a2, bk.z, s[2][2]); s[2][3] = fmaf(a2, bk.w, s[2][3]);
      s[3][0] = fmaf(a3, bk.x, s[3][0]); s[3][1] = fmaf(a3, bk.y, s[3][1]);
      s[3][2] = fmaf(a3, bk.z, s[3][2]); s[3][3] = fmaf(a3, bk.w, s[3][3]);
    }

    // scale + mask + per-row tile max
    float tmax[4];
#pragma unroll
    for (int i = 0; i < 4; i++) {
      const int4 mv = *(const int4*)&mask[((size_t)bb * NSEQ + q0 + qrow + i) * NSEQ +
                                          kb + kcol];
      s[i][0] = mv.x ? NEG_INF : s[i][0] * scale;
      s[i][1] = mv.y ? NEG_INF : s[i][1] * scale;
      s[i][2] = mv.z ? NEG_INF : s[i][2] * scale;
      s[i][3] = mv.w ? NEG_INF : s[i][3] * scale;
      tmax[i] = fmaxf(fmaxf(s[i][0], s[i][1]), fmaxf(s[i][2], s[i][3]));
    }
#pragma unroll
    for (int m = 8; m >= 1; m >>= 1)
#pragma unroll
      for (int i = 0; i < 4; i++)
        tmax[i] = fmaxf(tmax[i], __shfl_xor_sync(0xffffffffu, tmax[i], m, 16));

    // online softmax update (rmax clamped >= -1e30 => no NaN on all-masked tiles)
    float corr[4], tsum[4];
#pragma unroll
    for (int i = 0; i < 4; i++) {
      float nm = fmaxf(rmax[i], tmax[i]);
      corr[i] = __expf(rmax[i] - nm);
      rmax[i] = nm;
      float ts = 0.f;
#pragma unroll
      for (int j = 0; j < 4; j++) {
        s[i][j] = __expf(s[i][j] - nm);
        ts += s[i][j];
      }
      tsum[i] = ts;
    }
#pragma unroll
    for (int m = 8; m >= 1; m >>= 1)
#pragma unroll
      for (int i = 0; i < 4; i++)
        tsum[i] += __shfl_xor_sync(0xffffffffu, tsum[i], m, 16);
#pragma unroll
    for (int i = 0; i < 4; i++) {
      rsum[i] = rsum[i] * corr[i] + tsum[i];
#pragma unroll
      for (int j = 0; j < 4; j++) o[i][j] *= corr[i];
    }

    __syncthreads();  // everyone done reading KP-as-K
    // Stage P into KP as [q][k]
#pragma unroll
    for (int i = 0; i < 4; i++)
      *(float4*)&KP[(qrow + i) * 64 + kcol] =
          make_float4(s[i][0], s[i][1], s[i][2], s[i][3]);
    __syncthreads();

    // O += P @ V  (thread's 4 cols now index head dim c = kcol..kcol+3)
#pragma unroll 16
    for (int kk = 0; kk < 64; kk++) {
      float4 bv = *(const float4*)&Vs[kk * 64 + kcol];
      float a0 = KP[(qrow + 0) * 64 + kk];
      float a1 = KP[(qrow + 1) * 64 + kk];
      float a2 = KP[(qrow + 2) * 64 + kk];
      float a3 = KP[(qrow + 3) * 64 + kk];
      o[0][0] = fmaf(a0, bv.x, o[0][0]); o[0][1] = fmaf(a0, bv.y, o[0][1]);
      o[0][2] = fmaf(a0, bv.z, o[0][2]); o[0][3] = fmaf(a0, bv.w, o[0][3]);
      o[1][0] = fmaf(a1, bv.x, o[1][0]); o[1][1] = fmaf(a1, bv.y, o[1][1]);
      o[1][2] = fmaf(a1, bv.z, o[1][2]); o[1][3] = fmaf(a1, bv.w, o[1][3]);
      o[2][0] = fmaf(a2, bv.x, o[2][0]); o[2][1] = fmaf(a2, bv.y, o[2][1]);
      o[2][2] = fmaf(a2, bv.z, o[2][2]); o[2][3] = fmaf(a2, bv.w, o[2][3]);
      o[3][0] = fmaf(a3, bv.x, o[3][0]); o[3][1] = fmaf(a3, bv.y, o[3][1]);
      o[3][2] = fmaf(a3, bv.z, o[3][2]); o[3][3] = fmaf(a3, bv.w, o[3][3]);
    }
  }

  // finalize: divide by softmax denominator, write out
#pragma unroll
  for (int i = 0; i < 4; i++) {
    float inv = 1.f / rsum[i];
    float4 ov = make_float4(o[i][0] * inv, o[i][1] * inv, o[i][2] * inv,
                            o[i][3] * inv);
    *(float4*)&Og[(rowbase + q0 + qrow + i) * D + colbase + kcol] = ov;
  }
}

// ---------------------------------------------------------------------------
extern "C" void kernel_launch(void* const* d_in, const int* in_sizes, int n_in,
                              void* d_out, int out_size) {
  const float* x    = (const float*)d_in[0];
  const int*   mask = (const int*)d_in[1];
  const float* Wq   = (const float*)d_in[2];
  const float* Wk   = (const float*)d_in[3];
  const float* Wv   = (const float*)d_in[4];
  const float* Wp   = (const float*)d_in[5];
  const float* bp   = (const float*)d_in[6];
  float* out = (float*)d_out;

  float *pQ, *pK, *pV, *pO;
  cudaGetSymbolAddress((void**)&pQ, g_Q);
  cudaGetSymbolAddress((void**)&pK, g_K);
  cudaGetSymbolAddress((void**)&pV, g_V);
  cudaGetSymbolAddress((void**)&pO, g_O);

  dim3 gemm_grid(D / 128, M_TOTAL / 128);  // (8, 32)
  sgemm_kernel<<<gemm_grid, 256>>>(x, Wq, nullptr, pQ);
  sgemm_kernel<<<gemm_grid, 256>>>(x, Wk, nullptr, pK);
  sgemm_kernel<<<gemm_grid, 256>>>(x, Wv, nullptr, pV);

  attn_kernel<<<dim3(NSEQ / 64, NH, NB), 256>>>(pQ, pK, pV, mask, pO);

  sgemm_kernel<<<gemm_grid, 256>>>(pO, Wp, bp, out);
}

// round 3
// speedup vs baseline: 1.4128x; 1.4128x over previous
#include <cuda_runtime.h>
#include <cuda_bf16.h>
#include <cstdint>
#include <math.h>

#define D 1024
#define NSEQ 2048
#define NB 2
#define NH 16
#define HC 64
#define M_TOTAL (NB * NSEQ)  // 4096

// ---------------- scratch (allocation-free rule: __device__ globals) --------
__device__ __align__(256) float g_Q[M_TOTAL * D];
__device__ __align__(256) float g_K[M_TOTAL * D];
__device__ __align__(256) float g_V[M_TOTAL * D];
__device__ __align__(256) float g_O[M_TOTAL * D];
__device__ __align__(256) __nv_bfloat16 g_a1[M_TOTAL * D];  // activation hi
__device__ __align__(256) __nv_bfloat16 g_a2[M_TOTAL * D];  // activation lo
__device__ __align__(256) __nv_bfloat16 g_wt1[4 * D * D];   // W^T hi (q,k,v,p)
__device__ __align__(256) __nv_bfloat16 g_wt2[4 * D * D];   // W^T lo

// ---------------- PTX helpers (all base sm_80-class: safe on sm_100) -------
__device__ __forceinline__ uint32_t smem_u32(const void* p) {
  uint32_t a;
  asm("{ .reg .u64 t; cvta.to.shared.u64 t, %1; cvt.u32.u64 %0, t; }"
      : "=r"(a) : "l"(p));
  return a;
}

#define CP_ASYNC16(dst, src)                                          \
  asm volatile("cp.async.cg.shared.global [%0], [%1], 16;" ::"r"(dst), \
               "l"(src))
#define CP_COMMIT() asm volatile("cp.async.commit_group;")
#define CP_WAIT(n) asm volatile("cp.async.wait_group %0;" ::"n"(n))

#define LDSM4(r, a)                                                       \
  asm volatile("ldmatrix.sync.aligned.m8n8.x4.shared.b16 {%0,%1,%2,%3}, " \
               "[%4];"                                                    \
               : "=r"((r)[0]), "=r"((r)[1]), "=r"((r)[2]), "=r"((r)[3])   \
               : "r"(a))
#define LDSM2(r, a)                                                      \
  asm volatile("ldmatrix.sync.aligned.m8n8.x2.shared.b16 {%0,%1}, [%2];" \
               : "=r"((r)[0]), "=r"((r)[1])                              \
               : "r"(a))

#define MMA16816(d, a, b)                                                   \
  asm volatile(                                                             \
      "mma.sync.aligned.m16n8k16.row.col.f32.bf16.bf16.f32 "                \
      "{%0,%1,%2,%3}, {%4,%5,%6,%7}, {%8,%9}, {%0,%1,%2,%3};"               \
      : "+f"((d)[0]), "+f"((d)[1]), "+f"((d)[2]), "+f"((d)[3])              \
      : "r"((a)[0]), "r"((a)[1]), "r"((a)[2]), "r"((a)[3]), "r"((b)[0]),    \
        "r"((b)[1]))

// ---------------------------------------------------------------------------
// Prep kernels: fp32 -> (bf16 hi, bf16 lo)
// ---------------------------------------------------------------------------
__global__ __launch_bounds__(256) void split_kernel(
    const float* __restrict__ in, __nv_bfloat16* __restrict__ h,
    __nv_bfloat16* __restrict__ l, int n4) {
  int i = blockIdx.x * 256 + threadIdx.x;
  if (i >= n4) return;
  float4 v = ((const float4*)in)[i];
  __nv_bfloat16 h0 = __float2bfloat16(v.x);
  __nv_bfloat16 h1 = __float2bfloat16(v.y);
  __nv_bfloat16 h2 = __float2bfloat16(v.z);
  __nv_bfloat16 h3 = __float2bfloat16(v.w);
  __nv_bfloat16 l0 = __float2bfloat16(v.x - __bfloat162float(h0));
  __nv_bfloat16 l1 = __float2bfloat16(v.y - __bfloat162float(h1));
  __nv_bfloat16 l2 = __float2bfloat16(v.z - __bfloat162float(h2));
  __nv_bfloat16 l3 = __float2bfloat16(v.w - __bfloat162float(h3));
  __nv_bfloat162 hp0, hp1, lp0, lp1;
  hp0.x = h0; hp0.y = h1; hp1.x = h2; hp1.y = h3;
  lp0.x = l0; lp0.y = l1; lp1.x = l2; lp1.y = l3;
  ((__nv_bfloat162*)h)[2 * i] = hp0;
  ((__nv_bfloat162*)h)[2 * i + 1] = hp1;
  ((__nv_bfloat162*)l)[2 * i] = lp0;
  ((__nv_bfloat162*)l)[2 * i + 1] = lp1;
}

// W [K,N] fp32 -> T1/T2 [N,K] bf16 (transposed hi/lo)
__global__ __launch_bounds__(256) void transpose_split_kernel(
    const float* __restrict__ W, __nv_bfloat16* __restrict__ T1,
    __nv_bfloat16* __restrict__ T2) {
  __shared__ float t[32][33];
  int n0 = blockIdx.x * 32, k0 = blockIdx.y * 32;
  int tx = threadIdx.x, ty = threadIdx.y;  // 32 x 8
#pragma unroll
  for (int r = 0; r < 4; r++) {
    int k = k0 + ty + r * 8;
    t[ty + r * 8][tx] = W[(size_t)k * D + n0 + tx];
  }
  __syncthreads();
#pragma unroll
  for (int r = 0; r < 4; r++) {
    int n = n0 + ty + r * 8;
    float v = t[tx][ty + r * 8];
    __nv_bfloat16 h = __float2bfloat16(v);
    T1[(size_t)n * D + k0 + tx] = h;
    T2[(size_t)n * D + k0 + tx] = __float2bfloat16(v - __bfloat162float(h));
  }
}

// ---------------------------------------------------------------------------
// bf16 3-product GEMM via mma.sync (HMMA path, works on base sm_100 target):
//   C[M,1024] = (A1+A2) @ (B1+B2)^T (+ bias),  error ~2^-16 (l*l dropped)
//   A*: [4096,1024] bf16 row-major.  B*: [1024,1024] bf16 [N,K] row-major.
//   128x128 block, KC=64, 8 warps (2x4), warp tile 64x32, cp.async double buf.
// Smem per stage: A1(16K) A2(16K) B1(16K) B2(16K) = 64K; 2 stages = 128K.
// Layout: 128B rows (64 bf16), 16B granule swizzle g^(row&7).
// ---------------------------------------------------------------------------
#define GBM 128
#define GBN 128
#define GKC 64
#define GNIT (D / GKC)      // 16
#define STAGE_B 65536
#define GEMM_SMEM (2 * STAGE_B)

__global__ __launch_bounds__(256, 1) void gemm_mma_kernel(
    const __nv_bfloat16* __restrict__ A1, const __nv_bfloat16* __restrict__ A2,
    const __nv_bfloat16* __restrict__ B1, const __nv_bfloat16* __restrict__ B2,
    const float* __restrict__ bias, float* __restrict__ C) {
  extern __shared__ char sm_raw[];
  const uint32_t sbase = smem_u32(sm_raw);

  const int tid = threadIdx.x;
  const int wid = tid >> 5, lane = tid & 31;
  const int bm = blockIdx.y * GBM, bn = blockIdx.x * GBN;
  const int wm = (wid >> 2) * 64;   // warp M origin in tile
  const int wn = (wid & 3) * 32;    // warp N origin in tile

  float acc[4][4][4];
#pragma unroll
  for (int mi = 0; mi < 4; mi++)
#pragma unroll
    for (int ni = 0; ni < 4; ni++)
#pragma unroll
      for (int j = 0; j < 4; j++) acc[mi][ni][j] = 0.f;

  // ---- stage loader: 4 matrices x 1024 granules, 16 cp.async per thread ----
  auto load_stage = [&](int c) {
    const int kc = c * GKC;
    const uint32_t buf = sbase + (c & 1) * STAGE_B;
#pragma unroll
    for (int i = 0; i < 4; i++) {
      int gid = tid + i * 256;
      int row = gid >> 3, g = gid & 7;
      uint32_t ph = (uint32_t)(row * 128 + ((g ^ (row & 7)) << 4));
      const char* sA1 = (const char*)(A1 + (size_t)(bm + row) * D + kc + g * 8);
      const char* sA2 = (const char*)(A2 + (size_t)(bm + row) * D + kc + g * 8);
      const char* sB1 = (const char*)(B1 + (size_t)(bn + row) * D + kc + g * 8);
      const char* sB2 = (const char*)(B2 + (size_t)(bn + row) * D + kc + g * 8);
      CP_ASYNC16(buf + ph, sA1);
      CP_ASYNC16(buf + 16384 + ph, sA2);
      CP_ASYNC16(buf + 32768 + ph, sB1);
      CP_ASYNC16(buf + 49152 + ph, sB2);
    }
  };

  load_stage(0);
  CP_COMMIT();

  const int arow = ((lane >> 3) & 1) * 8 + (lane & 7);  // ldmatrix.x4 row
  const int asel = lane >> 4;                           // ldmatrix.x4 granule
  const int brow = lane & 7;                            // ldmatrix.x2 row
  const int bsel = (lane >> 3) & 1;                     // ldmatrix.x2 granule

  for (int c = 0; c < GNIT; c++) {
    if (c + 1 < GNIT) {
      load_stage(c + 1);
      CP_COMMIT();
      CP_WAIT(1);
    } else {
      CP_WAIT(0);
    }
    __syncthreads();

    const uint32_t buf = sbase + (c & 1) * STAGE_B;
    const uint32_t Ah = buf, Al = buf + 16384;
    const uint32_t Bh = buf + 32768, Bl = buf + 49152;

#pragma unroll
    for (int ks = 0; ks < 4; ks++) {
      uint32_t ah[4][4], al[4][4], bh[4][2], bl[4][2];
      const int ag = 2 * ks + asel;
      const int bg = 2 * ks + bsel;
#pragma unroll
      for (int mi = 0; mi < 4; mi++) {
        int row = wm + mi * 16 + arow;
        uint32_t off = (uint32_t)(row * 128 + ((ag ^ (row & 7)) << 4));
        LDSM4(ah[mi], Ah + off);
        LDSM4(al[mi], Al + off);
      }
#pragma unroll
      for (int ni = 0; ni < 4; ni++) {
        int row = wn + ni * 8 + brow;
        uint32_t off = (uint32_t)(row * 128 + ((bg ^ (row & 7)) << 4));
        LDSM2(bh[ni], Bh + off);
        LDSM2(bl[ni], Bl + off);
      }
#pragma unroll
      for (int mi = 0; mi < 4; mi++)
#pragma unroll
        for (int ni = 0; ni < 4; ni++) {
          MMA16816(acc[mi][ni], ah[mi], bh[ni]);
          MMA16816(acc[mi][ni], ah[mi], bl[ni]);
          MMA16816(acc[mi][ni], al[mi], bh[ni]);
        }
    }
    __syncthreads();
  }

  // ---- epilogue: fp32 accum -> C (+bias) ----
  const int r0 = lane >> 2, c0 = (lane & 3) * 2;
#pragma unroll
  for (int mi = 0; mi < 4; mi++) {
#pragma unroll
    for (int ni = 0; ni < 4; ni++) {
      int col = bn + wn + ni * 8 + c0;
      float b0 = bias ? bias[col] : 0.f;
      float b1 = bias ? bias[col + 1] : 0.f;
      int row = bm + wm + mi * 16 + r0;
      float2 v0 = make_float2(acc[mi][ni][0] + b0, acc[mi][ni][1] + b1);
      float2 v1 = make_float2(acc[mi][ni][2] + b0, acc[mi][ni][3] + b1);
      *(float2*)&C[(size_t)row * D + col] = v0;
      *(float2*)&C[(size_t)(row + 8) * D + col] = v1;
    }
  }
}

// ---------------------------------------------------------------------------
// Flash attention, fp32 (unchanged — passing at rel_err 1.1e-6).
// ---------------------------------------------------------------------------
__global__ __launch_bounds__(256) void attn_kernel(
    const float* __restrict__ Qg, const float* __restrict__ Kg,
    const float* __restrict__ Vg, const int* __restrict__ mask,
    float* __restrict__ Og) {
  __shared__ float Qs[64 * 64];
  __shared__ float KP[64 * 64];
  __shared__ float Vs[64 * 64];

  const int tid = threadIdx.x;
  const int qt = blockIdx.x;
  const int h = blockIdx.y;
  const int bb = blockIdx.z;
  const int ty = tid >> 4;
  const int tx = tid & 15;
  const int qrow = ty << 2;
  const int kcol = tx << 2;

  const int q0 = qt * 64;
  const size_t rowbase = (size_t)bb * NSEQ;
  const int colbase = h * HC;

#pragma unroll
  for (int r = 0; r < 4; r++) {
    int idx = tid + (r << 8);
    int q = idx >> 4;
    int c4 = (idx & 15) << 2;
    *(float4*)&Qs[q * 64 + c4] =
        *(const float4*)&Qg[(rowbase + q0 + q) * D + colbase + c4];
  }

  float o[4][4];
  float rmax[4], rsum[4];
#pragma unroll
  for (int i = 0; i < 4; i++) {
    rmax[i] = -1e30f;
    rsum[i] = 0.f;
#pragma unroll
    for (int j = 0; j < 4; j++) o[i][j] = 0.f;
  }

  const float scale = 0.125f;
  const float NEG_INF = __int_as_float(0xff800000);

  for (int kb = 0; kb < NSEQ; kb += 64) {
    __syncthreads();
#pragma unroll
    for (int r = 0; r < 4; r++) {
      int idx = tid + (r << 8);
      int k = idx >> 4;
      int c4 = (idx & 15) << 2;
      float4 kv = *(const float4*)&Kg[(rowbase + kb + k) * D + colbase + c4];
      int swz = ((c4 >> 2) & 7) << 2;
      int kp = k ^ swz;
      KP[(c4 + 0) * 64 + kp] = kv.x;
      KP[(c4 + 1) * 64 + kp] = kv.y;
      KP[(c4 + 2) * 64 + kp] = kv.z;
      KP[(c4 + 3) * 64 + kp] = kv.w;
      *(float4*)&Vs[k * 64 + c4] =
          *(const float4*)&Vg[(rowbase + kb + k) * D + colbase + c4];
    }
    __syncthreads();

    float s[4][4];
#pragma unroll
    for (int i = 0; i < 4; i++)
#pragma unroll
      for (int j = 0; j < 4; j++) s[i][j] = 0.f;

#pragma unroll 16
    for (int cc = 0; cc < 64; cc++) {
      int swz = ((cc >> 2) & 7) << 2;
      float4 bk = *(const float4*)&KP[cc * 64 + (kcol ^ swz)];
      float a0 = Qs[(qrow + 0) * 64 + cc];
      float a1 = Qs[(qrow + 1) * 64 + cc];
      float a2 = Qs[(qrow + 2) * 64 + cc];
      float a3 = Qs[(qrow + 3) * 64 + cc];
      s[0][0] = fmaf(a0, bk.x, s[0][0]); s[0][1] = fmaf(a0, bk.y, s[0][1]);
      s[0][2] = fmaf(a0, bk.z, s[0][2]); s[0][3] = fmaf(a0, bk.w, s[0][3]);
      s[1][0] = fmaf(a1, bk.x, s[1][0]); s[1][1] = fmaf(a1, bk.y, s[1][1]);
      s[1][2] = fmaf(a1, bk.z, s[1][2]); s[1][3] = fmaf(a1, bk.w, s[1][3]);
      s[2][0] = fmaf(a2, bk.x, s[2][0]); s[2][1] = fmaf(a2, bk.y, s[2][1]);
      s[2][2] = fmaf(a2, bk.z, s[2][2]); s[2][3] = fmaf(a2, bk.w, s[2][3]);
      s[3][0] = fmaf(a3, bk.x, s[3][0]); s[3][1] = fmaf(a3, bk.y, s[3][1]);
      s[3][2] = fmaf(a3, bk.z, s[3][2]); s[3][3] = fmaf(a3, bk.w, s[3][3]);
    }

    float tmax[4];
#pragma unroll
    for (int i = 0; i < 4; i++) {
      const int4 mv = *(const int4*)&mask[((size_t)bb * NSEQ + q0 + qrow + i) *
                                              NSEQ + kb + kcol];
      s[i][0] = mv.x ? NEG_INF : s[i][0] * scale;
      s[i][1] = mv.y ? NEG_INF : s[i][1] * scale;
      s[i][2] = mv.z ? NEG_INF : s[i][2] * scale;
      s[i][3] = mv.w ? NEG_INF : s[i][3] * scale;
      tmax[i] = fmaxf(fmaxf(s[i][0], s[i][1]), fmaxf(s[i][2], s[i][3]));
    }
#pragma unroll
    for (int m = 8; m >= 1; m >>= 1)
#pragma unroll
      for (int i = 0; i < 4; i++)
        tmax[i] = fmaxf(tmax[i], __shfl_xor_sync(0xffffffffu, tmax[i], m, 16));

    float corr[4], tsum[4];
#pragma unroll
    for (int i = 0; i < 4; i++) {
      float nm = fmaxf(rmax[i], tmax[i]);
      corr[i] = __expf(rmax[i] - nm);
      rmax[i] = nm;
      float ts = 0.f;
#pragma unroll
      for (int j = 0; j < 4; j++) {
        s[i][j] = __expf(s[i][j] - nm);
        ts += s[i][j];
      }
      tsum[i] = ts;
    }
#pragma unroll
    for (int m = 8; m >= 1; m >>= 1)
#pragma unroll
      for (int i = 0; i < 4; i++)
        tsum[i] += __shfl_xor_sync(0xffffffffu, tsum[i], m, 16);
#pragma unroll
    for (int i = 0; i < 4; i++) {
      rsum[i] = rsum[i] * corr[i] + tsum[i];
#pragma unroll
      for (int j = 0; j < 4; j++) o[i][j] *= corr[i];
    }

    __syncthreads();
#pragma unroll
    for (int i = 0; i < 4; i++)
      *(float4*)&KP[(qrow + i) * 64 + kcol] =
          make_float4(s[i][0], s[i][1], s[i][2], s[i][3]);
    __syncthreads();

#pragma unroll 16
    for (int kk = 0; kk < 64; kk++) {
      float4 bv = *(const float4*)&Vs[kk * 64 + kcol];
      float a0 = KP[(qrow + 0) * 64 + kk];
      float a1 = KP[(qrow + 1) * 64 + kk];
      float a2 = KP[(qrow + 2) * 64 + kk];
      float a3 = KP[(qrow + 3) * 64 + kk];
      o[0][0] = fmaf(a0, bv.x, o[0][0]); o[0][1] = fmaf(a0, bv.y, o[0][1]);
      o[0][2] = fmaf(a0, bv.z, o[0][2]); o[0][3] = fmaf(a0, bv.w, o[0][3]);
      o[1][0] = fmaf(a1, bv.x, o[1][0]); o[1][1] = fmaf(a1, bv.y, o[1][1]);
      o[1][2] = fmaf(a1, bv.z, o[1][2]); o[1][3] = fmaf(a1, bv.w, o[1][3]);
      o[2][0] = fmaf(a2, bv.x, o[2][0]); o[2][1] = fmaf(a2, bv.y, o[2][1]);
      o[2][2] = fmaf(a2, bv.z, o[2][2]); o[2][3] = fmaf(a2, bv.w, o[2][3]);
      o[3][0] = fmaf(a3, bv.x, o[3][0]); o[3][1] = fmaf(a3, bv.y, o[3][1]);
      o[3][2] = fmaf(a3, bv.z, o[3][2]); o[3][3] = fmaf(a3, bv.w, o[3][3]);
    }
  }

#pragma unroll
  for (int i = 0; i < 4; i++) {
    float inv = 1.f / rsum[i];
    float4 ov = make_float4(o[i][0] * inv, o[i][1] * inv, o[i][2] * inv,
                            o[i][3] * inv);
    *(float4*)&Og[(rowbase + q0 + qrow + i) * D + colbase + kcol] = ov;
  }
}

// ---------------------------------------------------------------------------
extern "C" void kernel_launch(void* const* d_in, const int* in_sizes, int n_in,
                              void* d_out, int out_size) {
  const float* x = (const float*)d_in[0];
  const int* mask = (const int*)d_in[1];
  const float* Wq = (const float*)d_in[2];
  const float* Wk = (const float*)d_in[3];
  const float* Wv = (const float*)d_in[4];
  const float* Wp = (const float*)d_in[5];
  const float* bp = (const float*)d_in[6];
  float* out = (float*)d_out;

  float *pQ, *pK, *pV, *pO;
  __nv_bfloat16 *pa1, *pa2, *pw1, *pw2;
  cudaGetSymbolAddress((void**)&pQ, g_Q);
  cudaGetSymbolAddress((void**)&pK, g_K);
  cudaGetSymbolAddress((void**)&pV, g_V);
  cudaGetSymbolAddress((void**)&pO, g_O);
  cudaGetSymbolAddress((void**)&pa1, g_a1);
  cudaGetSymbolAddress((void**)&pa2, g_a2);
  cudaGetSymbolAddress((void**)&pw1, g_wt1);
  cudaGetSymbolAddress((void**)&pw2, g_wt2);

  cudaFuncSetAttribute(gemm_mma_kernel,
                       cudaFuncAttributeMaxDynamicSharedMemorySize, GEMM_SMEM);

  // weight transpose + split (hi/lo bf16)
  dim3 tb(32, 8), tg(32, 32);
  transpose_split_kernel<<<tg, tb>>>(Wq, pw1 + 0 * D * D, pw2 + 0 * D * D);
  transpose_split_kernel<<<tg, tb>>>(Wk, pw1 + 1 * D * D, pw2 + 1 * D * D);
  transpose_split_kernel<<<tg, tb>>>(Wv, pw1 + 2 * D * D, pw2 + 2 * D * D);
  transpose_split_kernel<<<tg, tb>>>(Wp, pw1 + 3 * D * D, pw2 + 3 * D * D);

  // activation split
  split_kernel<<<(M_TOTAL * D / 4 + 255) / 256, 256>>>(x, pa1, pa2,
                                                       M_TOTAL * D / 4);

  dim3 gg(D / GBN, M_TOTAL / GBM);  // (8, 32)
  gemm_mma_kernel<<<gg, 256, GEMM_SMEM>>>(pa1, pa2, pw1 + 0 * D * D,
                                          pw2 + 0 * D * D, nullptr, pQ);
  gemm_mma_kernel<<<gg, 256, GEMM_SMEM>>>(pa1, pa2, pw1 + 1 * D * D,
                                          pw2 + 1 * D * D, nullptr, pK);
  gemm_mma_kernel<<<gg, 256, GEMM_SMEM>>>(pa1, pa2, pw1 + 2 * D * D,
                                          pw2 + 2 * D * D, nullptr, pV);

  attn_kernel<<<dim3(NSEQ / 64, NH, NB), 256>>>(pQ, pK, pV, mask, pO);

  split_kernel<<<(M_TOTAL * D / 4 + 255) / 256, 256>>>(pO, pa1, pa2,
                                                       M_TOTAL * D / 4);
  gemm_mma_kernel<<<gg, 256, GEMM_SMEM>>>(pa1, pa2, pw1 + 3 * D * D,
                                          pw2 + 3 * D * D, bp, out);
}

// round 4
// speedup vs baseline: 2.7837x; 1.9703x over previous
#include <cuda_runtime.h>
#include <cuda_bf16.h>
#include <cstdint>
#include <math.h>

#define D 1024
#define NSEQ 2048
#define NB 2
#define NH 16
#define HC 64
#define M_TOTAL (NB * NSEQ)  // 4096

// ---------------- scratch (allocation-free rule: __device__ globals) --------
__device__ __align__(256) __nv_bfloat16 g_a1[M_TOTAL * D];  // act hi / O hi
__device__ __align__(256) __nv_bfloat16 g_a2[M_TOTAL * D];  // act lo / O lo
__device__ __align__(256) __nv_bfloat16 g_qh[M_TOTAL * D];
__device__ __align__(256) __nv_bfloat16 g_ql[M_TOTAL * D];
__device__ __align__(256) __nv_bfloat16 g_kh[M_TOTAL * D];
__device__ __align__(256) __nv_bfloat16 g_kl[M_TOTAL * D];
__device__ __align__(256) __nv_bfloat16 g_vh[M_TOTAL * D];
__device__ __align__(256) __nv_bfloat16 g_vl[M_TOTAL * D];
__device__ __align__(256) __nv_bfloat16 g_wt1[4 * D * D];
__device__ __align__(256) __nv_bfloat16 g_wt2[4 * D * D];
__device__ __align__(256) uint32_t g_mbits[NB * NSEQ * (NSEQ / 32)];  // 1MB

// ---------------- PTX helpers ----------------------------------------------
__device__ __forceinline__ uint32_t smem_u32(const void* p) {
  uint32_t a;
  asm("{ .reg .u64 t; cvta.to.shared.u64 t, %1; cvt.u32.u64 %0, t; }"
      : "=r"(a) : "l"(p));
  return a;
}

#define CP_ASYNC16(dst, src)                                           \
  asm volatile("cp.async.cg.shared.global [%0], [%1], 16;" ::"r"(dst), \
               "l"(src))
#define CP_COMMIT() asm volatile("cp.async.commit_group;")
#define CP_WAIT(n) asm volatile("cp.async.wait_group %0;" ::"n"(n))

#define LDSM4(r, a)                                                       \
  asm volatile("ldmatrix.sync.aligned.m8n8.x4.shared.b16 {%0,%1,%2,%3}, " \
               "[%4];"                                                    \
               : "=r"((r)[0]), "=r"((r)[1]), "=r"((r)[2]), "=r"((r)[3])   \
               : "r"(a))
#define LDSM2(r, a)                                                      \
  asm volatile("ldmatrix.sync.aligned.m8n8.x2.shared.b16 {%0,%1}, [%2];" \
               : "=r"((r)[0]), "=r"((r)[1])                              \
               : "r"(a))
#define LDSM2T(r, a)                                                           \
  asm volatile("ldmatrix.sync.aligned.m8n8.x2.trans.shared.b16 {%0,%1}, [%2];" \
               : "=r"((r)[0]), "=r"((r)[1])                                    \
               : "r"(a))

#define MMA16816(d, a, b)                                                \
  asm volatile(                                                          \
      "mma.sync.aligned.m16n8k16.row.col.f32.bf16.bf16.f32 "             \
      "{%0,%1,%2,%3}, {%4,%5,%6,%7}, {%8,%9}, {%0,%1,%2,%3};"            \
      : "+f"((d)[0]), "+f"((d)[1]), "+f"((d)[2]), "+f"((d)[3])           \
      : "r"((a)[0]), "r"((a)[1]), "r"((a)[2]), "r"((a)[3]), "r"((b)[0]), \
        "r"((b)[1]))

__device__ __forceinline__ void split2(float a, float b, uint32_t& h,
                                       uint32_t& l) {
  __nv_bfloat162 hh = __floats2bfloat162_rn(a, b);
  float ra = a - __bfloat162float(hh.x);
  float rb = b - __bfloat162float(hh.y);
  __nv_bfloat162 ll = __floats2bfloat162_rn(ra, rb);
  h = *(uint32_t*)&hh;
  l = *(uint32_t*)&ll;
}

// ---------------------------------------------------------------------------
// Prep kernels
// ---------------------------------------------------------------------------
__global__ __launch_bounds__(256) void split_kernel(
    const float* __restrict__ in, __nv_bfloat16* __restrict__ h,
    __nv_bfloat16* __restrict__ l, int n4) {
  int i = blockIdx.x * 256 + threadIdx.x;
  if (i >= n4) return;
  float4 v = ((const float4*)in)[i];
  uint32_t h0, l0, h1, l1;
  split2(v.x, v.y, h0, l0);
  split2(v.z, v.w, h1, l1);
  ((uint32_t*)h)[2 * i] = h0;
  ((uint32_t*)h)[2 * i + 1] = h1;
  ((uint32_t*)l)[2 * i] = l0;
  ((uint32_t*)l)[2 * i + 1] = l1;
}

__global__ __launch_bounds__(256) void transpose_split_kernel(
    const float* __restrict__ W, __nv_bfloat16* __restrict__ T1,
    __nv_bfloat16* __restrict__ T2) {
  __shared__ float t[32][33];
  int n0 = blockIdx.x * 32, k0 = blockIdx.y * 32;
  int tx = threadIdx.x, ty = threadIdx.y;  // 32 x 8
#pragma unroll
  for (int r = 0; r < 4; r++) {
    int k = k0 + ty + r * 8;
    t[ty + r * 8][tx] = W[(size_t)k * D + n0 + tx];
  }
  __syncthreads();
#pragma unroll
  for (int r = 0; r < 4; r++) {
    int n = n0 + ty + r * 8;
    float v = t[tx][ty + r * 8];
    __nv_bfloat16 h = __float2bfloat16(v);
    T1[(size_t)n * D + k0 + tx] = h;
    T2[(size_t)n * D + k0 + tx] = __float2bfloat16(v - __bfloat162float(h));
  }
}

// mask int32 [2,2048,2048] -> 1 bit per element
__global__ __launch_bounds__(256) void maskbits_kernel(
    const int* __restrict__ mask, uint32_t* __restrict__ bits) {
  int wi = blockIdx.x * 256 + threadIdx.x;  // word index
  const int4* src = (const int4*)(mask + (size_t)wi * 32);
  uint32_t w = 0;
#pragma unroll
  for (int j = 0; j < 8; j++) {
    int4 m = src[j];
    w |= (m.x ? 1u : 0u) << (4 * j);
    w |= (m.y ? 1u : 0u) << (4 * j + 1);
    w |= (m.z ? 1u : 0u) << (4 * j + 2);
    w |= (m.w ? 1u : 0u) << (4 * j + 3);
  }
  bits[wi] = w;
}

// ---------------------------------------------------------------------------
// bf16 3-product GEMM (mma.sync). Epilogue: fp32+bias OR bf16 hi/lo split.
// ---------------------------------------------------------------------------
#define GBM 128
#define GBN 128
#define GKC 64
#define GNIT (D / GKC)  // 16
#define STAGE_B 65536
#define GEMM_SMEM (2 * STAGE_B)

__global__ __launch_bounds__(256, 1) void gemm_mma_kernel(
    const __nv_bfloat16* __restrict__ A1, const __nv_bfloat16* __restrict__ A2,
    const __nv_bfloat16* __restrict__ B1, const __nv_bfloat16* __restrict__ B2,
    const float* __restrict__ bias, float* __restrict__ C,
    __nv_bfloat16* __restrict__ Chi, __nv_bfloat16* __restrict__ Clo,
    float alpha) {
  extern __shared__ char sm_raw[];
  const uint32_t sbase = smem_u32(sm_raw);

  const int tid = threadIdx.x;
  const int wid = tid >> 5, lane = tid & 31;
  const int bm = blockIdx.y * GBM, bn = blockIdx.x * GBN;
  const int wm = (wid >> 2) * 64;
  const int wn = (wid & 3) * 32;

  float acc[4][4][4];
#pragma unroll
  for (int mi = 0; mi < 4; mi++)
#pragma unroll
    for (int ni = 0; ni < 4; ni++)
#pragma unroll
      for (int j = 0; j < 4; j++) acc[mi][ni][j] = 0.f;

  auto load_stage = [&](int c) {
    const int kc = c * GKC;
    const uint32_t buf = sbase + (c & 1) * STAGE_B;
#pragma unroll
    for (int i = 0; i < 4; i++) {
      int gid = tid + i * 256;
      int row = gid >> 3, g = gid & 7;
      uint32_t ph = (uint32_t)(row * 128 + ((g ^ (row & 7)) << 4));
      CP_ASYNC16(buf + ph, (const char*)(A1 + (size_t)(bm + row) * D + kc + g * 8));
      CP_ASYNC16(buf + 16384 + ph, (const char*)(A2 + (size_t)(bm + row) * D + kc + g * 8));
      CP_ASYNC16(buf + 32768 + ph, (const char*)(B1 + (size_t)(bn + row) * D + kc + g * 8));
      CP_ASYNC16(buf + 49152 + ph, (const char*)(B2 + (size_t)(bn + row) * D + kc + g * 8));
    }
  };

  load_stage(0);
  CP_COMMIT();

  const int arow = ((lane >> 3) & 1) * 8 + (lane & 7);
  const int asel = lane >> 4;
  const int brow = lane & 7;
  const int bsel = (lane >> 3) & 1;

  for (int c = 0; c < GNIT; c++) {
    if (c + 1 < GNIT) {
      load_stage(c + 1);
      CP_COMMIT();
      CP_WAIT(1);
    } else {
      CP_WAIT(0);
    }
    __syncthreads();

    const uint32_t buf = sbase + (c & 1) * STAGE_B;
    const uint32_t Ah = buf, Al = buf + 16384;
    const uint32_t Bh = buf + 32768, Bl = buf + 49152;

#pragma unroll
    for (int ks = 0; ks < 4; ks++) {
      uint32_t ah[4][4], al[4][4], bh[4][2], bl[4][2];
      const int ag = 2 * ks + asel;
      const int bg = 2 * ks + bsel;
#pragma unroll
      for (int mi = 0; mi < 4; mi++) {
        int row = wm + mi * 16 + arow;
        uint32_t off = (uint32_t)(row * 128 + ((ag ^ (row & 7)) << 4));
        LDSM4(ah[mi], Ah + off);
        LDSM4(al[mi], Al + off);
      }
#pragma unroll
      for (int ni = 0; ni < 4; ni++) {
        int row = wn + ni * 8 + brow;
        uint32_t off = (uint32_t)(row * 128 + ((bg ^ (row & 7)) << 4));
        LDSM2(bh[ni], Bh + off);
        LDSM2(bl[ni], Bl + off);
      }
#pragma unroll
      for (int mi = 0; mi < 4; mi++)
#pragma unroll
        for (int ni = 0; ni < 4; ni++) {
          MMA16816(acc[mi][ni], ah[mi], bh[ni]);
          MMA16816(acc[mi][ni], ah[mi], bl[ni]);
          MMA16816(acc[mi][ni], al[mi], bh[ni]);
        }
    }
    __syncthreads();
  }

  const int r0 = lane >> 2, c0 = (lane & 3) * 2;
  if (Chi) {
    // split epilogue: bf16 hi/lo, scaled by alpha
#pragma unroll
    for (int mi = 0; mi < 4; mi++) {
#pragma unroll
      for (int ni = 0; ni < 4; ni++) {
        int col = bn + wn + ni * 8 + c0;
        int row = bm + wm + mi * 16 + r0;
        uint32_t h0, l0, h1, l1;
        split2(acc[mi][ni][0] * alpha, acc[mi][ni][1] * alpha, h0, l0);
        split2(acc[mi][ni][2] * alpha, acc[mi][ni][3] * alpha, h1, l1);
        *(uint32_t*)&Chi[(size_t)row * D + col] = h0;
        *(uint32_t*)&Clo[(size_t)row * D + col] = l0;
        *(uint32_t*)&Chi[(size_t)(row + 8) * D + col] = h1;
        *(uint32_t*)&Clo[(size_t)(row + 8) * D + col] = l1;
      }
    }
  } else {
#pragma unroll
    for (int mi = 0; mi < 4; mi++) {
#pragma unroll
      for (int ni = 0; ni < 4; ni++) {
        int col = bn + wn + ni * 8 + c0;
        float b0 = bias ? bias[col] : 0.f;
        float b1 = bias ? bias[col + 1] : 0.f;
        int row = bm + wm + mi * 16 + r0;
        float2 v0 = make_float2(acc[mi][ni][0] + b0, acc[mi][ni][1] + b1);
        float2 v1 = make_float2(acc[mi][ni][2] + b0, acc[mi][ni][3] + b1);
        *(float2*)&C[(size_t)row * D + col] = v0;
        *(float2*)&C[(size_t)(row + 8) * D + col] = v1;
      }
    }
  }
}

// ---------------------------------------------------------------------------
// Flash attention via mma.sync bf16 3-product.
// CTA = (q-tile 128, head, batch); 8 warps, each owns 16 q rows x 128 keys.
// Smem: Qh/Ql (32K) + 2 stages x {Kh,Kl,Vh,Vl} (64K each) = 160K.
// Q pre-scaled by 1/8 in projection. Mask from bitmask (1 bit/elem).
// ---------------------------------------------------------------------------
#define ATTN_SMEM (32768 + 2 * 65536)

__global__ __launch_bounds__(256, 1) void attn_mma_kernel(
    const __nv_bfloat16* __restrict__ Qh, const __nv_bfloat16* __restrict__ Ql,
    const __nv_bfloat16* __restrict__ Kh, const __nv_bfloat16* __restrict__ Kl,
    const __nv_bfloat16* __restrict__ Vh, const __nv_bfloat16* __restrict__ Vl,
    const uint32_t* __restrict__ mbits, __nv_bfloat16* __restrict__ Oh,
    __nv_bfloat16* __restrict__ Ol) {
  extern __shared__ char sm_raw[];
  const uint32_t sb = smem_u32(sm_raw);
  const uint32_t sQh = sb, sQl = sb + 16384, sKV = sb + 32768;

  const int tid = threadIdx.x;
  const int wid = tid >> 5, lane = tid & 31;
  const int qw = wid * 16;
  const int q0 = blockIdx.x * 128;
  const int h = blockIdx.y;
  const int bb = blockIdx.z;
  const size_t rowbase = (size_t)bb * NSEQ;
  const int colbase = h * HC;

  // ---- Q tiles (once) ----
  {
    const __nv_bfloat16* gqh = Qh + (rowbase + q0) * D + colbase;
    const __nv_bfloat16* gql = Ql + (rowbase + q0) * D + colbase;
#pragma unroll
    for (int i = 0; i < 4; i++) {
      int idx = tid + 256 * i;
      int row = idx >> 3, g = idx & 7;
      uint32_t sw = (uint32_t)(row * 128 + ((g ^ (row & 7)) << 4));
      CP_ASYNC16(sQh + sw, (const char*)(gqh + (size_t)row * D + g * 8));
      CP_ASYNC16(sQl + sw, (const char*)(gql + (size_t)row * D + g * 8));
    }
    CP_COMMIT();
  }

  auto load_kv = [&](int c) {
    const int kb = c * 128;
    const uint32_t buf = sKV + (c & 1) * 65536;
#pragma unroll
    for (int i = 0; i < 4; i++) {
      int idx = tid + 256 * i;
      int row = idx >> 3, g = idx & 7;
      uint32_t sw = (uint32_t)(row * 128 + ((g ^ (row & 7)) << 4));
      size_t goff = (rowbase + kb + row) * D + colbase + g * 8;
      CP_ASYNC16(buf + sw, (const char*)(Kh + goff));
      CP_ASYNC16(buf + 16384 + sw, (const char*)(Kl + goff));
      CP_ASYNC16(buf + 32768 + sw, (const char*)(Vh + goff));
      CP_ASYNC16(buf + 49152 + sw, (const char*)(Vl + goff));
    }
  };

  load_kv(0);
  CP_COMMIT();
  CP_WAIT(1);  // Q group done
  __syncthreads();

  // ---- Q fragments (register-resident, loop invariant) ----
  const int arow = ((lane >> 3) & 1) * 8 + (lane & 7);
  const int asel = lane >> 4;
  uint32_t qfh[4][4], qfl[4][4];
#pragma unroll
  for (int ks = 0; ks < 4; ks++) {
    int row = qw + arow;
    int g = 2 * ks + asel;
    uint32_t off = (uint32_t)(row * 128 + ((g ^ (row & 7)) << 4));
    LDSM4(qfh[ks], sQh + off);
    LDSM4(qfl[ks], sQl + off);
  }

  float o[8][4];
#pragma unroll
  for (int cn = 0; cn < 8; cn++)
#pragma unroll
    for (int j = 0; j < 4; j++) o[cn][j] = 0.f;
  float rmaxA = -1e30f, rmaxB = -1e30f, rsumA = 0.f, rsumB = 0.f;

  const int brow = lane & 7;
  const int bsel = (lane >> 3) & 1;
  const int tig = lane & 3;
  const int grp = lane >> 2;
  const float NEG = __int_as_float(0xff800000);

  for (int c = 0; c < 16; c++) {
    if (c + 1 < 16) {
      load_kv(c + 1);
      CP_COMMIT();
      CP_WAIT(1);
    } else {
      CP_WAIT(0);
    }
    __syncthreads();
    const uint32_t buf = sKV + (c & 1) * 65536;

    // ---- S = Q K^T (scaled, since Q pre-scaled) ----
    float s[16][4];
#pragma unroll
    for (int nk = 0; nk < 16; nk++)
#pragma unroll
      for (int j = 0; j < 4; j++) s[nk][j] = 0.f;

#pragma unroll
    for (int nk = 0; nk < 16; nk++) {
      int row = 8 * nk + brow;
#pragma unroll
      for (int ks = 0; ks < 4; ks++) {
        int g = 2 * ks + bsel;
        uint32_t off = (uint32_t)(row * 128 + ((g ^ (row & 7)) << 4));
        uint32_t kfh[2], kfl[2];
        LDSM2(kfh, buf + off);
        LDSM2(kfl, buf + 16384 + off);
        MMA16816(s[nk], qfh[ks], kfh);
        MMA16816(s[nk], qfh[ks], kfl);
        MMA16816(s[nk], qfl[ks], kfh);
      }
    }

    // ---- mask (bitmask) ----
    {
      size_t rA = rowbase + q0 + qw + grp;
      uint4 mA = *(const uint4*)&mbits[rA * 64 + c * 4];
      uint4 mB = *(const uint4*)&mbits[(rA + 8) * 64 + c * 4];
      uint32_t wa[4] = {mA.x, mA.y, mA.z, mA.w};
      uint32_t wb[4] = {mB.x, mB.y, mB.z, mB.w};
#pragma unroll
      for (int nk = 0; nk < 16; nk++) {
        uint32_t a = wa[nk >> 2], b = wb[nk >> 2];
        int bit = 8 * (nk & 3) + 2 * tig;
        if ((a >> bit) & 1) s[nk][0] = NEG;
        if ((a >> (bit + 1)) & 1) s[nk][1] = NEG;
        if ((b >> bit) & 1) s[nk][2] = NEG;
        if ((b >> (bit + 1)) & 1) s[nk][3] = NEG;
      }
    }

    // ---- online softmax ----
    float tA = NEG, tB = NEG;
#pragma unroll
    for (int nk = 0; nk < 16; nk++) {
      tA = fmaxf(tA, fmaxf(s[nk][0], s[nk][1]));
      tB = fmaxf(tB, fmaxf(s[nk][2], s[nk][3]));
    }
    tA = fmaxf(tA, __shfl_xor_sync(0xffffffffu, tA, 1));
    tA = fmaxf(tA, __shfl_xor_sync(0xffffffffu, tA, 2));
    tB = fmaxf(tB, __shfl_xor_sync(0xffffffffu, tB, 1));
    tB = fmaxf(tB, __shfl_xor_sync(0xffffffffu, tB, 2));

    float nmA = fmaxf(rmaxA, tA), nmB = fmaxf(rmaxB, tB);
    float corrA = __expf(rmaxA - nmA), corrB = __expf(rmaxB - nmB);
    rmaxA = nmA;
    rmaxB = nmB;

    float sA = 0.f, sB = 0.f;
#pragma unroll
    for (int nk = 0; nk < 16; nk++) {
      s[nk][0] = __expf(s[nk][0] - nmA);
      s[nk][1] = __expf(s[nk][1] - nmA);
      s[nk][2] = __expf(s[nk][2] - nmB);
      s[nk][3] = __expf(s[nk][3] - nmB);
      sA += s[nk][0] + s[nk][1];
      sB += s[nk][2] + s[nk][3];
    }
    sA += __shfl_xor_sync(0xffffffffu, sA, 1);
    sA += __shfl_xor_sync(0xffffffffu, sA, 2);
    sB += __shfl_xor_sync(0xffffffffu, sB, 1);
    sB += __shfl_xor_sync(0xffffffffu, sB, 2);
    rsumA = rsumA * corrA + sA;
    rsumB = rsumB * corrB + sB;
#pragma unroll
    for (int cn = 0; cn < 8; cn++) {
      o[cn][0] *= corrA;
      o[cn][1] *= corrA;
      o[cn][2] *= corrB;
      o[cn][3] *= corrB;
    }

    // ---- O += P V ----
#pragma unroll
    for (int g = 0; g < 8; g++) {
      uint32_t ph[4], pl[4];
      split2(s[2 * g][0], s[2 * g][1], ph[0], pl[0]);
      split2(s[2 * g][2], s[2 * g][3], ph[1], pl[1]);
      split2(s[2 * g + 1][0], s[2 * g + 1][1], ph[2], pl[2]);
      split2(s[2 * g + 1][2], s[2 * g + 1][3], ph[3], pl[3]);
      int vrow = 16 * g + brow + 8 * bsel;
#pragma unroll
      for (int cn = 0; cn < 8; cn++) {
        uint32_t off = (uint32_t)(vrow * 128 + ((cn ^ (vrow & 7)) << 4));
        uint32_t vfh[2], vfl[2];
        LDSM2T(vfh, buf + 32768 + off);
        LDSM2T(vfl, buf + 49152 + off);
        MMA16816(o[cn], ph, vfh);
        MMA16816(o[cn], ph, vfl);
        MMA16816(o[cn], pl, vfh);
      }
    }
    __syncthreads();
  }

  // ---- epilogue: normalize, split hi/lo bf16 ----
  float invA = 1.f / rsumA, invB = 1.f / rsumB;
  size_t rowA = rowbase + q0 + qw + grp;
#pragma unroll
  for (int cn = 0; cn < 8; cn++) {
    int col = colbase + 8 * cn + 2 * tig;
    uint32_t h0, l0, h1, l1;
    split2(o[cn][0] * invA, o[cn][1] * invA, h0, l0);
    split2(o[cn][2] * invB, o[cn][3] * invB, h1, l1);
    *(uint32_t*)&Oh[rowA * D + col] = h0;
    *(uint32_t*)&Ol[rowA * D + col] = l0;
    *(uint32_t*)&Oh[(rowA + 8) * D + col] = h1;
    *(uint32_t*)&Ol[(rowA + 8) * D + col] = l1;
  }
}

// ---------------------------------------------------------------------------
extern "C" void kernel_launch(void* const* d_in, const int* in_sizes, int n_in,
                              void* d_out, int out_size) {
  const float* x = (const float*)d_in[0];
  const int* mask = (const int*)d_in[1];
  const float* Wq = (const float*)d_in[2];
  const float* Wk = (const float*)d_in[3];
  const float* Wv = (const float*)d_in[4];
  const float* Wp = (const float*)d_in[5];
  const float* bp = (const float*)d_in[6];
  float* out = (float*)d_out;

  __nv_bfloat16 *pa1, *pa2, *pqh, *pql, *pkh, *pkl, *pvh, *pvl, *pw1, *pw2;
  uint32_t* pmb;
  cudaGetSymbolAddress((void**)&pa1, g_a1);
  cudaGetSymbolAddress((void**)&pa2, g_a2);
  cudaGetSymbolAddress((void**)&pqh, g_qh);
  cudaGetSymbolAddress((void**)&pql, g_ql);
  cudaGetSymbolAddress((void**)&pkh, g_kh);
  cudaGetSymbolAddress((void**)&pkl, g_kl);
  cudaGetSymbolAddress((void**)&pvh, g_vh);
  cudaGetSymbolAddress((void**)&pvl, g_vl);
  cudaGetSymbolAddress((void**)&pw1, g_wt1);
  cudaGetSymbolAddress((void**)&pw2, g_wt2);
  cudaGetSymbolAddress((void**)&pmb, g_mbits);

  cudaFuncSetAttribute(gemm_mma_kernel,
                       cudaFuncAttributeMaxDynamicSharedMemorySize, GEMM_SMEM);
  cudaFuncSetAttribute(attn_mma_kernel,
                       cudaFuncAttributeMaxDynamicSharedMemorySize, ATTN_SMEM);

  dim3 tb(32, 8), tg(32, 32);
  transpose_split_kernel<<<tg, tb>>>(Wq, pw1 + 0 * D * D, pw2 + 0 * D * D);
  transpose_split_kernel<<<tg, tb>>>(Wk, pw1 + 1 * D * D, pw2 + 1 * D * D);
  transpose_split_kernel<<<tg, tb>>>(Wv, pw1 + 2 * D * D, pw2 + 2 * D * D);
  transpose_split_kernel<<<tg, tb>>>(Wp, pw1 + 3 * D * D, pw2 + 3 * D * D);

  split_kernel<<<(M_TOTAL * D / 4 + 255) / 256, 256>>>(x, pa1, pa2,
                                                       M_TOTAL * D / 4);
  maskbits_kernel<<<(NB * NSEQ * (NSEQ / 32)) / 256, 256>>>(mask, pmb);

  dim3 gg(D / GBN, M_TOTAL / GBM);  // (8, 32)
  // Q projection pre-scaled by 1/sqrt(HC) = 0.125
  gemm_mma_kernel<<<gg, 256, GEMM_SMEM>>>(pa1, pa2, pw1 + 0 * D * D,
                                          pw2 + 0 * D * D, nullptr, nullptr,
                                          pqh, pql, 0.125f);
  gemm_mma_kernel<<<gg, 256, GEMM_SMEM>>>(pa1, pa2, pw1 + 1 * D * D,
                                          pw2 + 1 * D * D, nullptr, nullptr,
                                          pkh, pkl, 1.0f);
  gemm_mma_kernel<<<gg, 256, GEMM_SMEM>>>(pa1, pa2, pw1 + 2 * D * D,
                                          pw2 + 2 * D * D, nullptr, nullptr,
                                          pvh, pvl, 1.0f);

  attn_mma_kernel<<<dim3(NSEQ / 128, NH, NB), 256, ATTN_SMEM>>>(
      pqh, pql, pkh, pkl, pvh, pvl, pmb, pa1, pa2);

  gemm_mma_kernel<<<gg, 256, GEMM_SMEM>>>(pa1, pa2, pw1 + 3 * D * D,
                                          pw2 + 3 * D * D, bp, out, nullptr,
                                          nullptr, 1.0f);
}

// round 5
// speedup vs baseline: 4.0229x; 1.4452x over previous
#include <cuda_runtime.h>
#include <cuda_bf16.h>
#include <cstdint>
#include <math.h>

#define D 1024
#define NSEQ 2048
#define NB 2
#define NH 16
#define HC 64
#define M_TOTAL (NB * NSEQ)  // 4096

// Q scale: 1/sqrt(64) * log2(e)  (softmax done in exp2 domain)
#define QSCALE 0.180336880f

// ---------------- scratch (allocation-free rule: __device__ globals) --------
__device__ __align__(256) __nv_bfloat16 g_a1[M_TOTAL * D];  // x hi / O hi
__device__ __align__(256) __nv_bfloat16 g_a2[M_TOTAL * D];  // x lo / O lo
__device__ __align__(256) unsigned short g_qf[M_TOTAL * D];  // fp16 Q (scaled)
__device__ __align__(256) unsigned short g_kf[M_TOTAL * D];  // fp16 K
__device__ __align__(256) unsigned short g_vf[M_TOTAL * D];  // fp16 V
__device__ __align__(256) __nv_bfloat16 g_wt1[4 * D * D];
__device__ __align__(256) __nv_bfloat16 g_wt2[4 * D * D];
__device__ __align__(256) uint32_t g_mbits[NB * NSEQ * (NSEQ / 32)];  // 1MB

// ---------------- PTX helpers ----------------------------------------------
__device__ __forceinline__ uint32_t smem_u32(const void* p) {
  uint32_t a;
  asm("{ .reg .u64 t; cvta.to.shared.u64 t, %1; cvt.u32.u64 %0, t; }"
      : "=r"(a) : "l"(p));
  return a;
}

#define CP_ASYNC16(dst, src)                                           \
  asm volatile("cp.async.cg.shared.global [%0], [%1], 16;" ::"r"(dst), \
               "l"(src))
#define CP_COMMIT() asm volatile("cp.async.commit_group;")
#define CP_WAIT(n) asm volatile("cp.async.wait_group %0;" ::"n"(n))

#define LDSM4(r, a)                                                       \
  asm volatile("ldmatrix.sync.aligned.m8n8.x4.shared.b16 {%0,%1,%2,%3}, " \
               "[%4];"                                                    \
               : "=r"((r)[0]), "=r"((r)[1]), "=r"((r)[2]), "=r"((r)[3])   \
               : "r"(a))
#define LDSM2(r, a)                                                      \
  asm volatile("ldmatrix.sync.aligned.m8n8.x2.shared.b16 {%0,%1}, [%2];" \
               : "=r"((r)[0]), "=r"((r)[1])                              \
               : "r"(a))
#define LDSM4T(r, a)                                                      \
  asm volatile(                                                           \
      "ldmatrix.sync.aligned.m8n8.x4.trans.shared.b16 {%0,%1,%2,%3}, "    \
      "[%4];"                                                             \
      : "=r"((r)[0]), "=r"((r)[1]), "=r"((r)[2]), "=r"((r)[3])            \
      : "r"(a))

// bf16 mma (projection GEMMs)
#define MMA16816(d, a, b)                                                \
  asm volatile(                                                          \
      "mma.sync.aligned.m16n8k16.row.col.f32.bf16.bf16.f32 "             \
      "{%0,%1,%2,%3}, {%4,%5,%6,%7}, {%8,%9}, {%0,%1,%2,%3};"            \
      : "+f"((d)[0]), "+f"((d)[1]), "+f"((d)[2]), "+f"((d)[3])           \
      : "r"((a)[0]), "r"((a)[1]), "r"((a)[2]), "r"((a)[3]), "r"((b)[0]), \
        "r"((b)[1]))
// fp16 mma (attention)
#define MMAH16816(d, a, b)                                               \
  asm volatile(                                                          \
      "mma.sync.aligned.m16n8k16.row.col.f32.f16.f16.f32 "               \
      "{%0,%1,%2,%3}, {%4,%5,%6,%7}, {%8,%9}, {%0,%1,%2,%3};"            \
      : "+f"((d)[0]), "+f"((d)[1]), "+f"((d)[2]), "+f"((d)[3])           \
      : "r"((a)[0]), "r"((a)[1]), "r"((a)[2]), "r"((a)[3]), "r"((b)[0]), \
        "r"((b)[1]))

// pack two fp32 -> f16x2 {lo, hi}
#define PACK_F16X2(d, hi, lo) \
  asm("cvt.rn.f16x2.f32 %0, %1, %2;" : "=r"(d) : "f"(hi), "f"(lo))

#define EX2(d, x) asm("ex2.approx.f32 %0, %1;" : "=f"(d) : "f"(x))

__device__ __forceinline__ void split2(float a, float b, uint32_t& h,
                                       uint32_t& l) {
  __nv_bfloat162 hh = __floats2bfloat162_rn(a, b);
  float ra = a - __bfloat162float(hh.x);
  float rb = b - __bfloat162float(hh.y);
  __nv_bfloat162 ll = __floats2bfloat162_rn(ra, rb);
  h = *(uint32_t*)&hh;
  l = *(uint32_t*)&ll;
}

// ---------------------------------------------------------------------------
// Prep kernels
// ---------------------------------------------------------------------------
__global__ __launch_bounds__(256) void split_kernel(
    const float* __restrict__ in, __nv_bfloat16* __restrict__ h,
    __nv_bfloat16* __restrict__ l, int n4) {
  int i = blockIdx.x * 256 + threadIdx.x;
  if (i >= n4) return;
  float4 v = ((const float4*)in)[i];
  uint32_t h0, l0, h1, l1;
  split2(v.x, v.y, h0, l0);
  split2(v.z, v.w, h1, l1);
  ((uint32_t*)h)[2 * i] = h0;
  ((uint32_t*)h)[2 * i + 1] = h1;
  ((uint32_t*)l)[2 * i] = l0;
  ((uint32_t*)l)[2 * i + 1] = l1;
}

__global__ __launch_bounds__(256) void transpose_split_kernel(
    const float* __restrict__ W, __nv_bfloat16* __restrict__ T1,
    __nv_bfloat16* __restrict__ T2) {
  __shared__ float t[32][33];
  int n0 = blockIdx.x * 32, k0 = blockIdx.y * 32;
  int tx = threadIdx.x, ty = threadIdx.y;  // 32 x 8
#pragma unroll
  for (int r = 0; r < 4; r++) {
    int k = k0 + ty + r * 8;
    t[ty + r * 8][tx] = W[(size_t)k * D + n0 + tx];
  }
  __syncthreads();
#pragma unroll
  for (int r = 0; r < 4; r++) {
    int n = n0 + ty + r * 8;
    float v = t[tx][ty + r * 8];
    __nv_bfloat16 h = __float2bfloat16(v);
    T1[(size_t)n * D + k0 + tx] = h;
    T2[(size_t)n * D + k0 + tx] = __float2bfloat16(v - __bfloat162float(h));
  }
}

__global__ __launch_bounds__(256) void maskbits_kernel(
    const int* __restrict__ mask, uint32_t* __restrict__ bits) {
  int wi = blockIdx.x * 256 + threadIdx.x;
  const int4* src = (const int4*)(mask + (size_t)wi * 32);
  uint32_t w = 0;
#pragma unroll
  for (int j = 0; j < 8; j++) {
    int4 m = src[j];
    w |= (m.x ? 1u : 0u) << (4 * j);
    w |= (m.y ? 1u : 0u) << (4 * j + 1);
    w |= (m.z ? 1u : 0u) << (4 * j + 2);
    w |= (m.w ? 1u : 0u) << (4 * j + 3);
  }
  bits[wi] = w;
}

// ---------------------------------------------------------------------------
// bf16 3-product GEMM mainloop (shared by both GEMM kernels via macro body)
// ---------------------------------------------------------------------------
#define GBM 128
#define GBN 128
#define GKC 64
#define GNIT (D / GKC)  // 16
#define STAGE_B 65536
#define GEMM_SMEM (2 * STAGE_B)

#define GEMM_MAINLOOP(A1, A2, B1, B2, bm, bn, acc)                            \
  extern __shared__ char sm_raw[];                                            \
  const uint32_t sbase = smem_u32(sm_raw);                                    \
  const int tid = threadIdx.x;                                                \
  const int wid = tid >> 5, lane = tid & 31;                                  \
  const int wm = (wid >> 2) * 64;                                             \
  const int wn = (wid & 3) * 32;                                              \
  float acc[4][4][4];                                                         \
  _Pragma("unroll") for (int mi = 0; mi < 4; mi++)                            \
      _Pragma("unroll") for (int ni = 0; ni < 4; ni++)                        \
      _Pragma("unroll") for (int j = 0; j < 4; j++) acc[mi][ni][j] = 0.f;     \
  auto load_stage = [&](int c) {                                              \
    const int kc = c * GKC;                                                   \
    const uint32_t buf = sbase + (c & 1) * STAGE_B;                           \
    _Pragma("unroll") for (int i = 0; i < 4; i++) {                           \
      int gid = tid + i * 256;                                                \
      int row = gid >> 3, g = gid & 7;                                        \
      uint32_t ph = (uint32_t)(row * 128 + ((g ^ (row & 7)) << 4));           \
      CP_ASYNC16(buf + ph,                                                    \
                 (const char*)(A1 + (size_t)(bm + row) * D + kc + g * 8));    \
      CP_ASYNC16(buf + 16384 + ph,                                            \
                 (const char*)(A2 + (size_t)(bm + row) * D + kc + g * 8));    \
      CP_ASYNC16(buf + 32768 + ph,                                            \
                 (const char*)(B1 + (size_t)(bn + row) * D + kc + g * 8));    \
      CP_ASYNC16(buf + 49152 + ph,                                            \
                 (const char*)(B2 + (size_t)(bn + row) * D + kc + g * 8));    \
    }                                                                         \
  };                                                                          \
  load_stage(0);                                                              \
  CP_COMMIT();                                                                \
  const int arow = ((lane >> 3) & 1) * 8 + (lane & 7);                        \
  const int asel = lane >> 4;                                                 \
  const int brow = lane & 7;                                                  \
  const int bsel = (lane >> 3) & 1;                                           \
  for (int c = 0; c < GNIT; c++) {                                            \
    if (c + 1 < GNIT) {                                                       \
      load_stage(c + 1);                                                      \
      CP_COMMIT();                                                            \
      CP_WAIT(1);                                                             \
    } else {                                                                  \
      CP_WAIT(0);                                                             \
    }                                                                         \
    __syncthreads();                                                          \
    const uint32_t buf = sbase + (c & 1) * STAGE_B;                           \
    const uint32_t Ah = buf, Al = buf + 16384;                                \
    const uint32_t Bh = buf + 32768, Bl = buf + 49152;                        \
    _Pragma("unroll") for (int ks = 0; ks < 4; ks++) {                        \
      uint32_t ah[4][4], al[4][4], bh[4][2], bl[4][2];                        \
      const int ag = 2 * ks + asel;                                           \
      const int bg = 2 * ks + bsel;                                           \
      _Pragma("unroll") for (int mi = 0; mi < 4; mi++) {                      \
        int row = wm + mi * 16 + arow;                                        \
        uint32_t off = (uint32_t)(row * 128 + ((ag ^ (row & 7)) << 4));       \
        LDSM4(ah[mi], Ah + off);                                              \
        LDSM4(al[mi], Al + off);                                              \
      }                                                                       \
      _Pragma("unroll") for (int ni = 0; ni < 4; ni++) {                      \
        int row = wn + ni * 8 + brow;                                         \
        uint32_t off = (uint32_t)(row * 128 + ((bg ^ (row & 7)) << 4));       \
        LDSM2(bh[ni], Bh + off);                                              \
        LDSM2(bl[ni], Bl + off);                                              \
      }                                                                       \
      _Pragma("unroll") for (int mi = 0; mi < 4; mi++)                        \
          _Pragma("unroll") for (int ni = 0; ni < 4; ni++) {                  \
        MMA16816(acc[mi][ni], ah[mi], bh[ni]);                                \
        MMA16816(acc[mi][ni], ah[mi], bl[ni]);                                \
        MMA16816(acc[mi][ni], al[mi], bh[ni]);                                \
      }                                                                       \
    }                                                                         \
    __syncthreads();                                                          \
  }

// QKV fused: gridDim.z selects weight/output; epilogue -> fp16 (scaled)
__global__ __launch_bounds__(256, 1) void gemm_qkv_kernel(
    const __nv_bfloat16* __restrict__ A1, const __nv_bfloat16* __restrict__ A2,
    const __nv_bfloat16* __restrict__ W1, const __nv_bfloat16* __restrict__ W2,
    unsigned short* __restrict__ Qf, unsigned short* __restrict__ Kf,
    unsigned short* __restrict__ Vf) {
  const int z = blockIdx.z;
  const __nv_bfloat16* B1 = W1 + (size_t)z * D * D;
  const __nv_bfloat16* B2 = W2 + (size_t)z * D * D;
  unsigned short* out = (z == 0) ? Qf : (z == 1) ? Kf : Vf;
  const float alpha = (z == 0) ? QSCALE : 1.0f;
  const int bm = blockIdx.y * GBM, bn = blockIdx.x * GBN;

  GEMM_MAINLOOP(A1, A2, B1, B2, bm, bn, acc)

  const int r0 = lane >> 2, c0 = (lane & 3) * 2;
#pragma unroll
  for (int mi = 0; mi < 4; mi++) {
#pragma unroll
    for (int ni = 0; ni < 4; ni++) {
      int col = bn + wn + ni * 8 + c0;
      int row = bm + wm + mi * 16 + r0;
      uint32_t p0, p1;
      PACK_F16X2(p0, acc[mi][ni][1] * alpha, acc[mi][ni][0] * alpha);
      PACK_F16X2(p1, acc[mi][ni][3] * alpha, acc[mi][ni][2] * alpha);
      *(uint32_t*)&out[(size_t)row * D + col] = p0;
      *(uint32_t*)&out[(size_t)(row + 8) * D + col] = p1;
    }
  }
}

// Final projection: fp32 + bias epilogue
__global__ __launch_bounds__(256, 1) void gemm_out_kernel(
    const __nv_bfloat16* __restrict__ A1, const __nv_bfloat16* __restrict__ A2,
    const __nv_bfloat16* __restrict__ B1, const __nv_bfloat16* __restrict__ B2,
    const float* __restrict__ bias, float* __restrict__ C) {
  const int bm = blockIdx.y * GBM, bn = blockIdx.x * GBN;

  GEMM_MAINLOOP(A1, A2, B1, B2, bm, bn, acc)

  const int r0 = lane >> 2, c0 = (lane & 3) * 2;
#pragma unroll
  for (int mi = 0; mi < 4; mi++) {
#pragma unroll
    for (int ni = 0; ni < 4; ni++) {
      int col = bn + wn + ni * 8 + c0;
      float b0 = bias[col], b1 = bias[col + 1];
      int row = bm + wm + mi * 16 + r0;
      float2 v0 = make_float2(acc[mi][ni][0] + b0, acc[mi][ni][1] + b1);
      float2 v1 = make_float2(acc[mi][ni][2] + b0, acc[mi][ni][3] + b1);
      *(float2*)&C[(size_t)row * D + col] = v0;
      *(float2*)&C[(size_t)(row + 8) * D + col] = v1;
    }
  }
}

// ---------------------------------------------------------------------------
// Flash attention, single-product fp16, fixed-max exp2 softmax.
// CTA = (128-q tile, head, batch); 8 warps x 16 q rows.
// Smem: Q 16K + 2 stages x (K 16K + V 16K) = 80K.
// Q pre-scaled by 0.125*log2(e). Mask: 1 bit/elem.
// ---------------------------------------------------------------------------
#define ATTN_SMEM (16384 + 2 * 32768)

__global__ __launch_bounds__(256, 1) void attn_mma_kernel(
    const unsigned short* __restrict__ Qf, const unsigned short* __restrict__ Kf,
    const unsigned short* __restrict__ Vf, const uint32_t* __restrict__ mbits,
    __nv_bfloat16* __restrict__ Oh, __nv_bfloat16* __restrict__ Ol) {
  extern __shared__ char sm_raw[];
  const uint32_t sb = smem_u32(sm_raw);
  const uint32_t sQ = sb, sKV = sb + 16384;

  const int tid = threadIdx.x;
  const int wid = tid >> 5, lane = tid & 31;
  const int qw = wid * 16;
  const int q0 = blockIdx.x * 128;
  const int h = blockIdx.y;
  const int bb = blockIdx.z;
  const size_t rowbase = (size_t)bb * NSEQ;
  const int colbase = h * HC;

  // ---- Q tile ----
  {
    const unsigned short* gq = Qf + (rowbase + q0) * D + colbase;
#pragma unroll
    for (int i = 0; i < 4; i++) {
      int idx = tid + 256 * i;
      int row = idx >> 3, g = idx & 7;
      uint32_t sw = (uint32_t)(row * 128 + ((g ^ (row & 7)) << 4));
      CP_ASYNC16(sQ + sw, (const char*)(gq + (size_t)row * D + g * 8));
    }
    CP_COMMIT();
  }

  auto load_kv = [&](int c) {
    const int kb = c * 128;
    const uint32_t buf = sKV + (c & 1) * 32768;
#pragma unroll
    for (int i = 0; i < 4; i++) {
      int idx = tid + 256 * i;
      int row = idx >> 3, g = idx & 7;
      uint32_t sw = (uint32_t)(row * 128 + ((g ^ (row & 7)) << 4));
      size_t goff = (rowbase + kb + row) * D + colbase + g * 8;
      CP_ASYNC16(buf + sw, (const char*)(Kf + goff));
      CP_ASYNC16(buf + 16384 + sw, (const char*)(Vf + goff));
    }
  };

  load_kv(0);
  CP_COMMIT();
  CP_WAIT(1);  // Q done
  __syncthreads();

  // ---- Q fragments ----
  const int arow = ((lane >> 3) & 1) * 8 + (lane & 7);
  const int asel = lane >> 4;
  uint32_t qf[4][4];
#pragma unroll
  for (int ks = 0; ks < 4; ks++) {
    int row = qw + arow;
    int g = 2 * ks + asel;
    uint32_t off = (uint32_t)(row * 128 + ((g ^ (row & 7)) << 4));
    LDSM4(qf[ks], sQ + off);
  }

  float o[8][4];
#pragma unroll
  for (int cn = 0; cn < 8; cn++)
#pragma unroll
    for (int j = 0; j < 4; j++) o[cn][j] = 0.f;
  float rsumA = 0.f, rsumB = 0.f;

  const int l7 = lane & 7;
  const int kmat = lane >> 3;          // 0..3 (K ldsm4 granule select)
  const int tig = lane & 3;
  const int grp = lane >> 2;
  const float NEG = __int_as_float(0xff800000);

  // per-lane constant address pieces
  const uint32_t kbase0 = (uint32_t)(l7 * 128 + ((kmat ^ l7) << 4));
  const uint32_t kbase1 = (uint32_t)(l7 * 128 + (((4 + kmat) ^ l7) << 4));
  const uint32_t vrowoff =
      (uint32_t)((l7 + 8 * ((lane >> 3) & 1)) * 128);  // within 16-row group
  const int vgsel = lane >> 4;  // 0/1: granule select for V ldsm4t

  for (int c = 0; c < 16; c++) {
    if (c + 1 < 16) {
      load_kv(c + 1);
      CP_COMMIT();
      CP_WAIT(1);
    } else {
      CP_WAIT(0);
    }
    __syncthreads();
    const uint32_t bufK = sKV + (c & 1) * 32768;
    const uint32_t bufV = bufK + 16384;

    // ---- S = Q K^T ----
    float s[16][4];
#pragma unroll
    for (int nk = 0; nk < 16; nk++) {
#pragma unroll
      for (int j = 0; j < 4; j++) s[nk][j] = 0.f;
      uint32_t ka[4], kb2[4];
      LDSM4(ka, bufK + kbase0 + nk * 1024);
      LDSM4(kb2, bufK + kbase1 + nk * 1024);
      MMAH16816(s[nk], qf[0], (&ka[0]));
      MMAH16816(s[nk], qf[1], (&ka[2]));
      MMAH16816(s[nk], qf[2], (&kb2[0]));
      MMAH16816(s[nk], qf[3], (&kb2[2]));
    }

    // ---- mask ----
    {
      size_t rA = rowbase + q0 + qw + grp;
      uint4 mA = *(const uint4*)&mbits[rA * 64 + c * 4];
      uint4 mB = *(const uint4*)&mbits[(rA + 8) * 64 + c * 4];
      uint32_t wa[4] = {mA.x, mA.y, mA.z, mA.w};
      uint32_t wb[4] = {mB.x, mB.y, mB.z, mB.w};
#pragma unroll
      for (int nk = 0; nk < 16; nk++) {
        uint32_t a = wa[nk >> 2], b = wb[nk >> 2];
        int bit = 8 * (nk & 3) + 2 * tig;
        if ((a >> bit) & 1) s[nk][0] = NEG;
        if ((a >> (bit + 1)) & 1) s[nk][1] = NEG;
        if ((b >> bit) & 1) s[nk][2] = NEG;
        if ((b >> (bit + 1)) & 1) s[nk][3] = NEG;
      }
    }

    // ---- exp2 (logits already in log2 domain; fixed max = 0) ----
#pragma unroll
    for (int nk = 0; nk < 16; nk++) {
      EX2(s[nk][0], s[nk][0]);
      EX2(s[nk][1], s[nk][1]);
      EX2(s[nk][2], s[nk][2]);
      EX2(s[nk][3], s[nk][3]);
      rsumA += s[nk][0] + s[nk][1];
      rsumB += s[nk][2] + s[nk][3];
    }

    // ---- O += P V ----
#pragma unroll
    for (int g = 0; g < 8; g++) {
      uint32_t pa[4];
      PACK_F16X2(pa[0], s[2 * g][1], s[2 * g][0]);
      PACK_F16X2(pa[1], s[2 * g][3], s[2 * g][2]);
      PACK_F16X2(pa[2], s[2 * g + 1][1], s[2 * g + 1][0]);
      PACK_F16X2(pa[3], s[2 * g + 1][3], s[2 * g + 1][2]);
      const uint32_t vrow_base = bufV + (uint32_t)(g * 2048) + vrowoff;
#pragma unroll
      for (int cnp = 0; cnp < 4; cnp++) {
        int gc = 2 * cnp + vgsel;
        uint32_t off = (uint32_t)((gc ^ l7) << 4);
        uint32_t vf4[4];
        LDSM4T(vf4, vrow_base + off);
        MMAH16816(o[2 * cnp], pa, (&vf4[0]));
        MMAH16816(o[2 * cnp + 1], pa, (&vf4[2]));
      }
    }
    __syncthreads();
  }

  // ---- epilogue: quad-reduce sums, normalize, split hi/lo bf16 ----
  rsumA += __shfl_xor_sync(0xffffffffu, rsumA, 1);
  rsumA += __shfl_xor_sync(0xffffffffu, rsumA, 2);
  rsumB += __shfl_xor_sync(0xffffffffu, rsumB, 1);
  rsumB += __shfl_xor_sync(0xffffffffu, rsumB, 2);
  float invA = 1.f / rsumA, invB = 1.f / rsumB;
  size_t rowA = rowbase + q0 + qw + grp;
#pragma unroll
  for (int cn = 0; cn < 8; cn++) {
    int col = colbase + 8 * cn + 2 * tig;
    uint32_t h0, l0, h1, l1;
    split2(o[cn][0] * invA, o[cn][1] * invA, h0, l0);
    split2(o[cn][2] * invB, o[cn][3] * invB, h1, l1);
    *(uint32_t*)&Oh[rowA * D + col] = h0;
    *(uint32_t*)&Ol[rowA * D + col] = l0;
    *(uint32_t*)&Oh[(rowA + 8) * D + col] = h1;
    *(uint32_t*)&Ol[(rowA + 8) * D + col] = l1;
  }
}

// ---------------------------------------------------------------------------
extern "C" void kernel_launch(void* const* d_in, const int* in_sizes, int n_in,
                              void* d_out, int out_size) {
  const float* x = (const float*)d_in[0];
  const int* mask = (const int*)d_in[1];
  const float* Wq = (const float*)d_in[2];
  const float* Wk = (const float*)d_in[3];
  const float* Wv = (const float*)d_in[4];
  const float* Wp = (const float*)d_in[5];
  const float* bp = (const float*)d_in[6];
  float* out = (float*)d_out;

  __nv_bfloat16 *pa1, *pa2, *pw1, *pw2;
  unsigned short *pqf, *pkf, *pvf;
  uint32_t* pmb;
  cudaGetSymbolAddress((void**)&pa1, g_a1);
  cudaGetSymbolAddress((void**)&pa2, g_a2);
  cudaGetSymbolAddress((void**)&pqf, g_qf);
  cudaGetSymbolAddress((void**)&pkf, g_kf);
  cudaGetSymbolAddress((void**)&pvf, g_vf);
  cudaGetSymbolAddress((void**)&pw1, g_wt1);
  cudaGetSymbolAddress((void**)&pw2, g_wt2);
  cudaGetSymbolAddress((void**)&pmb, g_mbits);

  cudaFuncSetAttribute(gemm_qkv_kernel,
                       cudaFuncAttributeMaxDynamicSharedMemorySize, GEMM_SMEM);
  cudaFuncSetAttribute(gemm_out_kernel,
                       cudaFuncAttributeMaxDynamicSharedMemorySize, GEMM_SMEM);
  cudaFuncSetAttribute(attn_mma_kernel,
                       cudaFuncAttributeMaxDynamicSharedMemorySize, ATTN_SMEM);

  dim3 tb(32, 8), tg(32, 32);
  transpose_split_kernel<<<tg, tb>>>(Wq, pw1 + 0 * D * D, pw2 + 0 * D * D);
  transpose_split_kernel<<<tg, tb>>>(Wk, pw1 + 1 * D * D, pw2 + 1 * D * D);
  transpose_split_kernel<<<tg, tb>>>(Wv, pw1 + 2 * D * D, pw2 + 2 * D * D);
  transpose_split_kernel<<<tg, tb>>>(Wp, pw1 + 3 * D * D, pw2 + 3 * D * D);

  split_kernel<<<(M_TOTAL * D / 4 + 255) / 256, 256>>>(x, pa1, pa2,
                                                       M_TOTAL * D / 4);
  maskbits_kernel<<<(NB * NSEQ * (NSEQ / 32)) / 256, 256>>>(mask, pmb);

  dim3 gqkv(D / GBN, M_TOTAL / GBM, 3);  // (8, 32, 3)
  gemm_qkv_kernel<<<gqkv, 256, GEMM_SMEM>>>(pa1, pa2, pw1, pw2, pqf, pkf, pvf);

  attn_mma_kernel<<<dim3(NSEQ / 128, NH, NB), 256, ATTN_SMEM>>>(
      pqf, pkf, pvf, pmb, pa1, pa2);

  dim3 gg(D / GBN, M_TOTAL / GBM);  // (8, 32)
  gemm_out_kernel<<<gg, 256, GEMM_SMEM>>>(pa1, pa2, pw1 + 3 * D * D,
                                          pw2 + 3 * D * D, bp, out);
}

// round 6
// speedup vs baseline: 4.1682x; 1.0361x over previous
#include <cuda_runtime.h>
#include <cuda_bf16.h>
#include <cuda_fp16.h>
#include <cstdint>
#include <math.h>

#define D 1024
#define NSEQ 2048
#define NB 2
#define NH 16
#define HC 64
#define M_TOTAL (NB * NSEQ)  // 4096

// Q scale: 1/sqrt(64) * log2(e)  (softmax in exp2 domain, fixed max = 0)
#define QSCALE 0.180336880f

// ---------------- scratch (allocation-free rule: __device__ globals) --------
__device__ __align__(256) __nv_bfloat16 g_a1[M_TOTAL * D];  // x hi / O hi
__device__ __align__(256) __nv_bfloat16 g_a2[M_TOTAL * D];  // x lo / O lo
__device__ __align__(256) unsigned short g_qf[M_TOTAL * D];  // fp16 Q (scaled)
__device__ __align__(256) unsigned short g_kf[M_TOTAL * D];  // fp16 K
__device__ __align__(256) unsigned short g_vf[M_TOTAL * D];  // fp16 V
__device__ __align__(256) __nv_bfloat16 g_wt1[4 * D * D];
__device__ __align__(256) __nv_bfloat16 g_wt2[4 * D * D];
__device__ __align__(256) unsigned short g_mf[NB * NSEQ * NSEQ];  // fp16 0/1

// ---------------- PTX helpers ----------------------------------------------
__device__ __forceinline__ uint32_t smem_u32(const void* p) {
  uint32_t a;
  asm("{ .reg .u64 t; cvta.to.shared.u64 t, %1; cvt.u32.u64 %0, t; }"
      : "=r"(a) : "l"(p));
  return a;
}

#define CP_ASYNC16(dst, src)                                           \
  asm volatile("cp.async.cg.shared.global [%0], [%1], 16;" ::"r"(dst), \
               "l"(src))
#define CP_COMMIT() asm volatile("cp.async.commit_group;")
#define CP_WAIT(n) asm volatile("cp.async.wait_group %0;" ::"n"(n))

#define LDSM4(r, a)                                                       \
  asm volatile("ldmatrix.sync.aligned.m8n8.x4.shared.b16 {%0,%1,%2,%3}, " \
               "[%4];"                                                    \
               : "=r"((r)[0]), "=r"((r)[1]), "=r"((r)[2]), "=r"((r)[3])   \
               : "r"(a))
#define LDSM2(r, a)                                                      \
  asm volatile("ldmatrix.sync.aligned.m8n8.x2.shared.b16 {%0,%1}, [%2];" \
               : "=r"((r)[0]), "=r"((r)[1])                              \
               : "r"(a))
#define LDSM4T(r, a)                                                      \
  asm volatile(                                                           \
      "ldmatrix.sync.aligned.m8n8.x4.trans.shared.b16 {%0,%1,%2,%3}, "    \
      "[%4];"                                                             \
      : "=r"((r)[0]), "=r"((r)[1]), "=r"((r)[2]), "=r"((r)[3])            \
      : "r"(a))

#define MMA16816(d, a, b)                                                \
  asm volatile(                                                          \
      "mma.sync.aligned.m16n8k16.row.col.f32.bf16.bf16.f32 "             \
      "{%0,%1,%2,%3}, {%4,%5,%6,%7}, {%8,%9}, {%0,%1,%2,%3};"            \
      : "+f"((d)[0]), "+f"((d)[1]), "+f"((d)[2]), "+f"((d)[3])           \
      : "r"((a)[0]), "r"((a)[1]), "r"((a)[2]), "r"((a)[3]), "r"((b)[0]), \
        "r"((b)[1]))
#define MMAH16816(d, a, b)                                               \
  asm volatile(                                                          \
      "mma.sync.aligned.m16n8k16.row.col.f32.f16.f16.f32 "               \
      "{%0,%1,%2,%3}, {%4,%5,%6,%7}, {%8,%9}, {%0,%1,%2,%3};"            \
      : "+f"((d)[0]), "+f"((d)[1]), "+f"((d)[2]), "+f"((d)[3])           \
      : "r"((a)[0]), "r"((a)[1]), "r"((a)[2]), "r"((a)[3]), "r"((b)[0]), \
        "r"((b)[1]))

#define PACK_F16X2(d, hi, lo) \
  asm("cvt.rn.f16x2.f32 %0, %1, %2;" : "=r"(d) : "f"(hi), "f"(lo))
#define HMUL2(d, a, b) \
  asm("mul.f16x2 %0, %1, %2;" : "=r"(d) : "r"(a), "r"(b))
#define EX2(d, x) asm("ex2.approx.f32 %0, %1;" : "=f"(d) : "f"(x))

__device__ __forceinline__ void split2(float a, float b, uint32_t& h,
                                       uint32_t& l) {
  __nv_bfloat162 hh = __floats2bfloat162_rn(a, b);
  float ra = a - __bfloat162float(hh.x);
  float rb = b - __bfloat162float(hh.y);
  __nv_bfloat162 ll = __floats2bfloat162_rn(ra, rb);
  h = *(uint32_t*)&hh;
  l = *(uint32_t*)&ll;
}

// ---------------------------------------------------------------------------
// Prep kernels
// ---------------------------------------------------------------------------
__global__ __launch_bounds__(256) void split_kernel(
    const float* __restrict__ in, __nv_bfloat16* __restrict__ h,
    __nv_bfloat16* __restrict__ l, int n4) {
  int i = blockIdx.x * 256 + threadIdx.x;
  if (i >= n4) return;
  float4 v = ((const float4*)in)[i];
  uint32_t h0, l0, h1, l1;
  split2(v.x, v.y, h0, l0);
  split2(v.z, v.w, h1, l1);
  ((uint32_t*)h)[2 * i] = h0;
  ((uint32_t*)h)[2 * i + 1] = h1;
  ((uint32_t*)l)[2 * i] = l0;
  ((uint32_t*)l)[2 * i + 1] = l1;
}

// fused 4-weight transpose+split: z selects Wq/Wk/Wv/Wp
__global__ __launch_bounds__(256) void transpose_split_kernel(
    const float* __restrict__ Wq, const float* __restrict__ Wk,
    const float* __restrict__ Wv, const float* __restrict__ Wp,
    __nv_bfloat16* __restrict__ T1, __nv_bfloat16* __restrict__ T2) {
  __shared__ float t[32][33];
  const int z = blockIdx.z;
  const float* W = (z == 0) ? Wq : (z == 1) ? Wk : (z == 2) ? Wv : Wp;
  __nv_bfloat16* O1 = T1 + (size_t)z * D * D;
  __nv_bfloat16* O2 = T2 + (size_t)z * D * D;
  int n0 = blockIdx.x * 32, k0 = blockIdx.y * 32;
  int tx = threadIdx.x, ty = threadIdx.y;  // 32 x 8
#pragma unroll
  for (int r = 0; r < 4; r++) {
    int k = k0 + ty + r * 8;
    t[ty + r * 8][tx] = W[(size_t)k * D + n0 + tx];
  }
  __syncthreads();
#pragma unroll
  for (int r = 0; r < 4; r++) {
    int n = n0 + ty + r * 8;
    float v = t[tx][ty + r * 8];
    __nv_bfloat16 h = __float2bfloat16(v);
    O1[(size_t)n * D + k0 + tx] = h;
    O2[(size_t)n * D + k0 + tx] = __float2bfloat16(v - __bfloat162float(h));
  }
}

// mask int32 -> fp16 multiplier: nonzero -> 0.0, zero -> 1.0
__global__ __launch_bounds__(256) void maskf16_kernel(
    const int* __restrict__ mask, unsigned short* __restrict__ mf) {
  size_t i = ((size_t)blockIdx.x * 256 + threadIdx.x) * 8;
  const int4* src = (const int4*)(mask + i);
  int4 m0 = src[0], m1 = src[1];
  union {
    unsigned short h[8];
    uint4 v;
  } u;
  u.h[0] = m0.x ? 0 : 0x3C00;
  u.h[1] = m0.y ? 0 : 0x3C00;
  u.h[2] = m0.z ? 0 : 0x3C00;
  u.h[3] = m0.w ? 0 : 0x3C00;
  u.h[4] = m1.x ? 0 : 0x3C00;
  u.h[5] = m1.y ? 0 : 0x3C00;
  u.h[6] = m1.z ? 0 : 0x3C00;
  u.h[7] = m1.w ? 0 : 0x3C00;
  *(uint4*)(mf + i) = u.v;
}

// ---------------------------------------------------------------------------
// bf16 3-product GEMM mainloop (macro body shared by both GEMM kernels)
// ---------------------------------------------------------------------------
#define GBM 128
#define GBN 128
#define GKC 64
#define GNIT (D / GKC)  // 16
#define STAGE_B 65536
#define GEMM_SMEM (2 * STAGE_B)

#define GEMM_MAINLOOP(A1, A2, B1, B2, bm, bn, acc)                            \
  extern __shared__ char sm_raw[];                                            \
  const uint32_t sbase = smem_u32(sm_raw);                                    \
  const int tid = threadIdx.x;                                                \
  const int wid = tid >> 5, lane = tid & 31;                                  \
  const int wm = (wid >> 2) * 64;                                             \
  const int wn = (wid & 3) * 32;                                              \
  float acc[4][4][4];                                                         \
  _Pragma("unroll") for (int mi = 0; mi < 4; mi++)                            \
      _Pragma("unroll") for (int ni = 0; ni < 4; ni++)                        \
      _Pragma("unroll") for (int j = 0; j < 4; j++) acc[mi][ni][j] = 0.f;     \
  auto load_stage = [&](int c) {                                              \
    const int kc = c * GKC;                                                   \
    const uint32_t buf = sbase + (c & 1) * STAGE_B;                           \
    _Pragma("unroll") for (int i = 0; i < 4; i++) {                           \
      int gid = tid + i * 256;                                                \
      int row = gid >> 3, g = gid & 7;                                        \
      uint32_t ph = (uint32_t)(row * 128 + ((g ^ (row & 7)) << 4));           \
      CP_ASYNC16(buf + ph,                                                    \
                 (const char*)(A1 + (size_t)(bm + row) * D + kc + g * 8));    \
      CP_ASYNC16(buf + 16384 + ph,                                            \
                 (const char*)(A2 + (size_t)(bm + row) * D + kc + g * 8));    \
      CP_ASYNC16(buf + 32768 + ph,                                            \
                 (const char*)(B1 + (size_t)(bn + row) * D + kc + g * 8));    \
      CP_ASYNC16(buf + 49152 + ph,                                            \
                 (const char*)(B2 + (size_t)(bn + row) * D + kc + g * 8));    \
    }                                                                         \
  };                                                                          \
  load_stage(0);                                                              \
  CP_COMMIT();                                                                \
  const int arow = ((lane >> 3) & 1) * 8 + (lane & 7);                        \
  const int asel = lane >> 4;                                                 \
  const int brow = lane & 7;                                                  \
  const int bsel = (lane >> 3) & 1;                                           \
  for (int c = 0; c < GNIT; c++) {                                            \
    if (c + 1 < GNIT) {                                                       \
      load_stage(c + 1);                                                      \
      CP_COMMIT();                                                            \
      CP_WAIT(1);                                                             \
    } else {                                                                  \
      CP_WAIT(0);                                                             \
    }                                                                         \
    __syncthreads();                                                          \
    const uint32_t buf = sbase + (c & 1) * STAGE_B;                           \
    const uint32_t Ah = buf, Al = buf + 16384;                                \
    const uint32_t Bh = buf + 32768, Bl = buf + 49152;                        \
    _Pragma("unroll") for (int ks = 0; ks < 4; ks++) {                        \
      uint32_t ah[4][4], al[4][4], bh[4][2], bl[4][2];                        \
      const int ag = 2 * ks + asel;                                           \
      const int bg = 2 * ks + bsel;                                           \
      _Pragma("unroll") for (int mi = 0; mi < 4; mi++) {                      \
        int row = wm + mi * 16 + arow;                                        \
        uint32_t off = (uint32_t)(row * 128 + ((ag ^ (row & 7)) << 4));       \
        LDSM4(ah[mi], Ah + off);                                              \
        LDSM4(al[mi], Al + off);                                              \
      }                                                                       \
      _Pragma("unroll") for (int ni = 0; ni < 4; ni++) {                      \
        int row = wn + ni * 8 + brow;                                         \
        uint32_t off = (uint32_t)(row * 128 + ((bg ^ (row & 7)) << 4));       \
        LDSM2(bh[ni], Bh + off);                                              \
        LDSM2(bl[ni], Bl + off);                                              \
      }                                                                       \
      _Pragma("unroll") for (int mi = 0; mi < 4; mi++)                        \
          _Pragma("unroll") for (int ni = 0; ni < 4; ni++) {                  \
        MMA16816(acc[mi][ni], ah[mi], bh[ni]);                                \
        MMA16816(acc[mi][ni], ah[mi], bl[ni]);                                \
        MMA16816(acc[mi][ni], al[mi], bh[ni]);                                \
      }                                                                       \
    }                                                                         \
    __syncthreads();                                                          \
  }

__global__ __launch_bounds__(256, 1) void gemm_qkv_kernel(
    const __nv_bfloat16* __restrict__ A1, const __nv_bfloat16* __restrict__ A2,
    const __nv_bfloat16* __restrict__ W1, const __nv_bfloat16* __restrict__ W2,
    unsigned short* __restrict__ Qf, unsigned short* __restrict__ Kf,
    unsigned short* __restrict__ Vf) {
  const int z = blockIdx.z;
  const __nv_bfloat16* B1 = W1 + (size_t)z * D * D;
  const __nv_bfloat16* B2 = W2 + (size_t)z * D * D;
  unsigned short* out = (z == 0) ? Qf : (z == 1) ? Kf : Vf;
  const float alpha = (z == 0) ? QSCALE : 1.0f;
  const int bm = blockIdx.y * GBM, bn = blockIdx.x * GBN;

  GEMM_MAINLOOP(A1, A2, B1, B2, bm, bn, acc)

  const int r0 = lane >> 2, c0 = (lane & 3) * 2;
#pragma unroll
  for (int mi = 0; mi < 4; mi++) {
#pragma unroll
    for (int ni = 0; ni < 4; ni++) {
      int col = bn + wn + ni * 8 + c0;
      int row = bm + wm + mi * 16 + r0;
      uint32_t p0, p1;
      PACK_F16X2(p0, acc[mi][ni][1] * alpha, acc[mi][ni][0] * alpha);
      PACK_F16X2(p1, acc[mi][ni][3] * alpha, acc[mi][ni][2] * alpha);
      *(uint32_t*)&out[(size_t)row * D + col] = p0;
      *(uint32_t*)&out[(size_t)(row + 8) * D + col] = p1;
    }
  }
}

__global__ __launch_bounds__(256, 1) void gemm_out_kernel(
    const __nv_bfloat16* __restrict__ A1, const __nv_bfloat16* __restrict__ A2,
    const __nv_bfloat16* __restrict__ B1, const __nv_bfloat16* __restrict__ B2,
    const float* __restrict__ bias, float* __restrict__ C) {
  const int bm = blockIdx.y * GBM, bn = blockIdx.x * GBN;

  GEMM_MAINLOOP(A1, A2, B1, B2, bm, bn, acc)

  const int r0 = lane >> 2, c0 = (lane & 3) * 2;
#pragma unroll
  for (int mi = 0; mi < 4; mi++) {
#pragma unroll
    for (int ni = 0; ni < 4; ni++) {
      int col = bn + wn + ni * 8 + c0;
      float b0 = bias[col], b1 = bias[col + 1];
      int row = bm + wm + mi * 16 + r0;
      float2 v0 = make_float2(acc[mi][ni][0] + b0, acc[mi][ni][1] + b1);
      float2 v1 = make_float2(acc[mi][ni][2] + b0, acc[mi][ni][3] + b1);
      *(float2*)&C[(size_t)row * D + col] = v0;
      *(float2*)&C[(size_t)(row + 8) * D + col] = v1;
    }
  }
}

// ---------------------------------------------------------------------------
// Flash attention: fp16 single-product mma, fixed-max exp2 softmax,
// fp16 multiplier mask applied post-exp via HMUL2, row sums via ones-MMA.
// CTA = (128-q tile, head, batch); 8 warps x 16 q rows.
// Smem: Q 16K + 2 stages x (K 16K + V 16K + M 32K) = 144K.
// ---------------------------------------------------------------------------
#define ATTN_STAGE 65536
#define ATTN_SMEM (16384 + 2 * ATTN_STAGE)  // 147456

__global__ __launch_bounds__(256, 1) void attn_mma_kernel(
    const unsigned short* __restrict__ Qf, const unsigned short* __restrict__ Kf,
    const unsigned short* __restrict__ Vf, const unsigned short* __restrict__ Mf,
    __nv_bfloat16* __restrict__ Oh, __nv_bfloat16* __restrict__ Ol) {
  extern __shared__ char sm_raw[];
  const uint32_t sb = smem_u32(sm_raw);
  const uint32_t sQ = sb, sKV = sb + 16384;

  const int tid = threadIdx.x;
  const int wid = tid >> 5, lane = tid & 31;
  const int qw = wid * 16;
  const int q0 = blockIdx.x * 128;
  const int h = blockIdx.y;
  const int bb = blockIdx.z;
  const size_t rowbase = (size_t)bb * NSEQ;
  const int colbase = h * HC;

  // ---- Q tile ----
  {
    const unsigned short* gq = Qf + (rowbase + q0) * D + colbase;
#pragma unroll
    for (int i = 0; i < 4; i++) {
      int idx = tid + 256 * i;
      int row = idx >> 3, g = idx & 7;
      uint32_t sw = (uint32_t)(row * 128 + ((g ^ (row & 7)) << 4));
      CP_ASYNC16(sQ + sw, (const char*)(gq + (size_t)row * D + g * 8));
    }
    CP_COMMIT();
  }

  // stage layout: K at +0 (16K), V at +16384 (16K), M at +32768 (32K)
  auto load_kv = [&](int c) {
    const int kb = c * 128;
    const uint32_t buf = sKV + (c & 1) * ATTN_STAGE;
#pragma unroll
    for (int i = 0; i < 4; i++) {
      int idx = tid + 256 * i;
      int row = idx >> 3, g = idx & 7;
      uint32_t sw = (uint32_t)(row * 128 + ((g ^ (row & 7)) << 4));
      size_t goff = (rowbase + kb + row) * D + colbase + g * 8;
      CP_ASYNC16(buf + sw, (const char*)(Kf + goff));
      CP_ASYNC16(buf + 16384 + sw, (const char*)(Vf + goff));
    }
    // mask tile: rows = q (128), 256B/row (128 fp16 k-values)
    const unsigned short* gm = Mf + (rowbase + q0) * NSEQ + kb;
#pragma unroll
    for (int i = 0; i < 8; i++) {
      int idx = tid + 256 * i;
      int row = idx >> 4, gg = idx & 15;
      uint32_t sw = (uint32_t)(row * 256 + ((gg ^ (row & 7)) << 4));
      CP_ASYNC16(buf + 32768 + sw,
                 (const char*)(gm + (size_t)row * NSEQ + gg * 8));
    }
  };

  load_kv(0);
  CP_COMMIT();
  CP_WAIT(1);  // Q done
  __syncthreads();

  // ---- Q fragments ----
  const int arow = ((lane >> 3) & 1) * 8 + (lane & 7);
  const int asel = lane >> 4;
  uint32_t qf[4][4];
#pragma unroll
  for (int ks = 0; ks < 4; ks++) {
    int row = qw + arow;
    int g = 2 * ks + asel;
    uint32_t off = (uint32_t)(row * 128 + ((g ^ (row & 7)) << 4));
    LDSM4(qf[ks], sQ + off);
  }

  float o[8][4];
#pragma unroll
  for (int cn = 0; cn < 8; cn++)
#pragma unroll
    for (int j = 0; j < 4; j++) o[cn][j] = 0.f;
  float osum[4] = {0.f, 0.f, 0.f, 0.f};

  const int l7 = lane & 7;
  const int kmat = lane >> 3;
  const int tig = lane & 3;
  const int grp = lane >> 2;

  const uint32_t kbase0 = (uint32_t)(l7 * 128 + ((kmat ^ l7) << 4));
  const uint32_t kbase1 = (uint32_t)(l7 * 128 + (((4 + kmat) ^ l7) << 4));
  const uint32_t vrowoff = (uint32_t)((l7 + 8 * ((lane >> 3) & 1)) * 128);
  const int vgsel = lane >> 4;
  // mask fragment address pieces (A-frag layout, 256B rows)
  const int mrow = qw + arow;
  const uint32_t mbase = (uint32_t)(mrow * 256);
  const int mr7 = mrow & 7;
  const uint32_t ones2[2] = {0x3C003C00u, 0x3C003C00u};

  for (int c = 0; c < 16; c++) {
    if (c + 1 < 16) {
      load_kv(c + 1);
      CP_COMMIT();
      CP_WAIT(1);
    } else {
      CP_WAIT(0);
    }
    __syncthreads();
    const uint32_t bufK = sKV + (c & 1) * ATTN_STAGE;
    const uint32_t bufV = bufK + 16384;
    const uint32_t bufM = bufK + 32768;

    // ---- S = Q K^T (no masking needed pre-exp) ----
    float s[16][4];
#pragma unroll
    for (int nk = 0; nk < 16; nk++) {
#pragma unroll
      for (int j = 0; j < 4; j++) s[nk][j] = 0.f;
      uint32_t ka[4], kb2[4];
      LDSM4(ka, bufK + kbase0 + nk * 1024);
      LDSM4(kb2, bufK + kbase1 + nk * 1024);
      MMAH16816(s[nk], qf[0], (&ka[0]));
      MMAH16816(s[nk], qf[1], (&ka[2]));
      MMAH16816(s[nk], qf[2], (&kb2[0]));
      MMAH16816(s[nk], qf[3], (&kb2[2]));
    }

    // ---- exp2 (log2 domain, fixed max 0) ----
#pragma unroll
    for (int nk = 0; nk < 16; nk++) {
      EX2(s[nk][0], s[nk][0]);
      EX2(s[nk][1], s[nk][1]);
      EX2(s[nk][2], s[nk][2]);
      EX2(s[nk][3], s[nk][3]);
    }

    // ---- P = exp * mask;  rowsum via ones-MMA;  O += P V ----
#pragma unroll
    for (int g = 0; g < 8; g++) {
      uint32_t pa[4], ma[4];
      PACK_F16X2(pa[0], s[2 * g][1], s[2 * g][0]);
      PACK_F16X2(pa[1], s[2 * g][3], s[2 * g][2]);
      PACK_F16X2(pa[2], s[2 * g + 1][1], s[2 * g + 1][0]);
      PACK_F16X2(pa[3], s[2 * g + 1][3], s[2 * g + 1][2]);
      LDSM4(ma, bufM + mbase + (uint32_t)(((2 * g + asel) ^ mr7) << 4));
      HMUL2(pa[0], pa[0], ma[0]);
      HMUL2(pa[1], pa[1], ma[1]);
      HMUL2(pa[2], pa[2], ma[2]);
      HMUL2(pa[3], pa[3], ma[3]);
      MMAH16816(osum, pa, ones2);
      const uint32_t vrow_base = bufV + (uint32_t)(g * 2048) + vrowoff;
#pragma unroll
      for (int cnp = 0; cnp < 4; cnp++) {
        int gc = 2 * cnp + vgsel;
        uint32_t off = (uint32_t)((gc ^ l7) << 4);
        uint32_t vf4[4];
        LDSM4T(vf4, vrow_base + off);
        MMAH16816(o[2 * cnp], pa, (&vf4[0]));
        MMAH16816(o[2 * cnp + 1], pa, (&vf4[2]));
      }
    }
    __syncthreads();
  }

  // ---- epilogue: osum[0]/osum[2] are full row sums (MMA k-reduced) ----
  float invA = 1.f / osum[0], invB = 1.f / osum[2];
  size_t rowA = rowbase + q0 + qw + grp;
#pragma unroll
  for (int cn = 0; cn < 8; cn++) {
    int col = colbase + 8 * cn + 2 * tig;
    uint32_t h0, l0, h1, l1;
    split2(o[cn][0] * invA, o[cn][1] * invA, h0, l0);
    split2(o[cn][2] * invB, o[cn][3] * invB, h1, l1);
    *(uint32_t*)&Oh[rowA * D + col] = h0;
    *(uint32_t*)&Ol[rowA * D + col] = l0;
    *(uint32_t*)&Oh[(rowA + 8) * D + col] = h1;
    *(uint32_t*)&Ol[(rowA + 8) * D + col] = l1;
  }
}

// ---------------------------------------------------------------------------
extern "C" void kernel_launch(void* const* d_in, const int* in_sizes, int n_in,
                              void* d_out, int out_size) {
  const float* x = (const float*)d_in[0];
  const int* mask = (const int*)d_in[1];
  const float* Wq = (const float*)d_in[2];
  const float* Wk = (const float*)d_in[3];
  const float* Wv = (const float*)d_in[4];
  const float* Wp = (const float*)d_in[5];
  const float* bp = (const float*)d_in[6];
  float* out = (float*)d_out;

  __nv_bfloat16 *pa1, *pa2, *pw1, *pw2;
  unsigned short *pqf, *pkf, *pvf, *pmf;
  cudaGetSymbolAddress((void**)&pa1, g_a1);
  cudaGetSymbolAddress((void**)&pa2, g_a2);
  cudaGetSymbolAddress((void**)&pqf, g_qf);
  cudaGetSymbolAddress((void**)&pkf, g_kf);
  cudaGetSymbolAddress((void**)&pvf, g_vf);
  cudaGetSymbolAddress((void**)&pw1, g_wt1);
  cudaGetSymbolAddress((void**)&pw2, g_wt2);
  cudaGetSymbolAddress((void**)&pmf, g_mf);

  cudaFuncSetAttribute(gemm_qkv_kernel,
                       cudaFuncAttributeMaxDynamicSharedMemorySize, GEMM_SMEM);
  cudaFuncSetAttribute(gemm_out_kernel,
                       cudaFuncAttributeMaxDynamicSharedMemorySize, GEMM_SMEM);
  cudaFuncSetAttribute(attn_mma_kernel,
                       cudaFuncAttributeMaxDynamicSharedMemorySize, ATTN_SMEM);

  dim3 tb(32, 8), tg(32, 32, 4);
  transpose_split_kernel<<<tg, tb>>>(Wq, Wk, Wv, Wp, pw1, pw2);

  split_kernel<<<(M_TOTAL * D / 4 + 255) / 256, 256>>>(x, pa1, pa2,
                                                       M_TOTAL * D / 4);
  maskf16_kernel<<<(NB * NSEQ * NSEQ / 8) / 256, 256>>>(mask, pmf);

  dim3 gqkv(D / GBN, M_TOTAL / GBM, 3);  // (8, 32, 3)
  gemm_qkv_kernel<<<gqkv, 256, GEMM_SMEM>>>(pa1, pa2, pw1, pw2, pqf, pkf, pvf);

  attn_mma_kernel<<<dim3(NSEQ / 128, NH, NB), 256, ATTN_SMEM>>>(
      pqf, pkf, pvf, pmf, pa1, pa2);

  dim3 gg(D / GBN, M_TOTAL / GBM);  // (8, 32)
  gemm_out_kernel<<<gg, 256, GEMM_SMEM>>>(pa1, pa2, pw1 + 3 * D * D,
                                          pw2 + 3 * D * D, bp, out);
}

// round 7
// speedup vs baseline: 6.9794x; 1.6744x over previous
#include <cuda_runtime.h>
#include <cuda_bf16.h>
#include <cuda_fp16.h>
#include <cstdint>
#include <math.h>

#define D 1024
#define NSEQ 2048
#define NB 2
#define NH 16
#define HC 64
#define M_TOTAL (NB * NSEQ)  // 4096

// Q scale: 1/sqrt(64) * log2(e)  (softmax in exp2 domain, fixed max = 0)
#define QSCALE 0.180336880f

// ---------------- scratch (allocation-free rule: __device__ globals) --------
__device__ __align__(256) unsigned short g_xf[M_TOTAL * D];  // fp16 x
__device__ __align__(256) unsigned short g_qf[M_TOTAL * D];  // fp16 Q (scaled)
__device__ __align__(256) unsigned short g_kf[M_TOTAL * D];  // fp16 K
__device__ __align__(256) unsigned short g_vf[M_TOTAL * D];  // fp16 V
__device__ __align__(256) unsigned short g_of[M_TOTAL * D];  // fp16 attn out
__device__ __align__(256) unsigned short g_wtf[4 * D * D];   // fp16 W^T x4
__device__ __align__(256) unsigned short g_mf[NB * NSEQ * NSEQ];  // fp16 0/1

// ---------------- PTX helpers ----------------------------------------------
__device__ __forceinline__ uint32_t smem_u32(const void* p) {
  uint32_t a;
  asm("{ .reg .u64 t; cvta.to.shared.u64 t, %1; cvt.u32.u64 %0, t; }"
      : "=r"(a) : "l"(p));
  return a;
}

#define CP_ASYNC16(dst, src)                                           \
  asm volatile("cp.async.cg.shared.global [%0], [%1], 16;" ::"r"(dst), \
               "l"(src))
#define CP_COMMIT() asm volatile("cp.async.commit_group;")
#define CP_WAIT(n) asm volatile("cp.async.wait_group %0;" ::"n"(n))

#define LDSM4(r, a)                                                       \
  asm volatile("ldmatrix.sync.aligned.m8n8.x4.shared.b16 {%0,%1,%2,%3}, " \
               "[%4];"                                                    \
               : "=r"((r)[0]), "=r"((r)[1]), "=r"((r)[2]), "=r"((r)[3])   \
               : "r"(a))
#define LDSM2(r, a)                                                      \
  asm volatile("ldmatrix.sync.aligned.m8n8.x2.shared.b16 {%0,%1}, [%2];" \
               : "=r"((r)[0]), "=r"((r)[1])                              \
               : "r"(a))
#define LDSM4T(r, a)                                                      \
  asm volatile(                                                           \
      "ldmatrix.sync.aligned.m8n8.x4.trans.shared.b16 {%0,%1,%2,%3}, "    \
      "[%4];"                                                             \
      : "=r"((r)[0]), "=r"((r)[1]), "=r"((r)[2]), "=r"((r)[3])            \
      : "r"(a))

#define MMAH16816(d, a, b)                                               \
  asm volatile(                                                          \
      "mma.sync.aligned.m16n8k16.row.col.f32.f16.f16.f32 "               \
      "{%0,%1,%2,%3}, {%4,%5,%6,%7}, {%8,%9}, {%0,%1,%2,%3};"            \
      : "+f"((d)[0]), "+f"((d)[1]), "+f"((d)[2]), "+f"((d)[3])           \
      : "r"((a)[0]), "r"((a)[1]), "r"((a)[2]), "r"((a)[3]), "r"((b)[0]), \
        "r"((b)[1]))

#define PACK_F16X2(d, hi, lo) \
  asm("cvt.rn.f16x2.f32 %0, %1, %2;" : "=r"(d) : "f"(hi), "f"(lo))
#define HMUL2(d, a, b) \
  asm("mul.f16x2 %0, %1, %2;" : "=r"(d) : "r"(a), "r"(b))
#define EX2(d, x) asm("ex2.approx.f32 %0, %1;" : "=f"(d) : "f"(x))

// ---------------------------------------------------------------------------
// Prep kernels
// ---------------------------------------------------------------------------
__global__ __launch_bounds__(256) void cvt_f16_kernel(
    const float* __restrict__ in, unsigned short* __restrict__ o, int n4) {
  int i = blockIdx.x * 256 + threadIdx.x;
  if (i >= n4) return;
  float4 v = ((const float4*)in)[i];
  uint32_t p0, p1;
  PACK_F16X2(p0, v.y, v.x);
  PACK_F16X2(p1, v.w, v.z);
  ((uint2*)o)[i] = make_uint2(p0, p1);
}

// fused 4-weight transpose: z selects Wq/Wk/Wv/Wp; fp32 [K,N] -> fp16 [N,K]
__global__ __launch_bounds__(256) void transpose_f16_kernel(
    const float* __restrict__ Wq, const float* __restrict__ Wk,
    const float* __restrict__ Wv, const float* __restrict__ Wp,
    unsigned short* __restrict__ T) {
  __shared__ float t[32][33];
  const int z = blockIdx.z;
  const float* W = (z == 0) ? Wq : (z == 1) ? Wk : (z == 2) ? Wv : Wp;
  unsigned short* O = T + (size_t)z * D * D;
  int n0 = blockIdx.x * 32, k0 = blockIdx.y * 32;
  int tx = threadIdx.x, ty = threadIdx.y;  // 32 x 8
#pragma unroll
  for (int r = 0; r < 4; r++) {
    int k = k0 + ty + r * 8;
    t[ty + r * 8][tx] = W[(size_t)k * D + n0 + tx];
  }
  __syncthreads();
#pragma unroll
  for (int r = 0; r < 4; r++) {
    int n = n0 + ty + r * 8;
    O[(size_t)n * D + k0 + tx] = __half_as_ushort(__float2half_rn(t[tx][ty + r * 8]));
  }
}

// mask int32 -> fp16 multiplier: nonzero -> 0.0, zero -> 1.0
__global__ __launch_bounds__(256) void maskf16_kernel(
    const int* __restrict__ mask, unsigned short* __restrict__ mf) {
  size_t i = ((size_t)blockIdx.x * 256 + threadIdx.x) * 8;
  const int4* src = (const int4*)(mask + i);
  int4 m0 = src[0], m1 = src[1];
  union {
    unsigned short h[8];
    uint4 v;
  } u;
  u.h[0] = m0.x ? 0 : 0x3C00;
  u.h[1] = m0.y ? 0 : 0x3C00;
  u.h[2] = m0.z ? 0 : 0x3C00;
  u.h[3] = m0.w ? 0 : 0x3C00;
  u.h[4] = m1.x ? 0 : 0x3C00;
  u.h[5] = m1.y ? 0 : 0x3C00;
  u.h[6] = m1.z ? 0 : 0x3C00;
  u.h[7] = m1.w ? 0 : 0x3C00;
  *(uint4*)(mf + i) = u.v;
}

// ---------------------------------------------------------------------------
// fp16 single-product GEMM: C[M,1024] = A @ B^T.
// 128x128 block, KC=64, 8 warps (2x4), warp tile 64x32, cp.async double buf.
// Stage = A(16K) + B(16K) = 32K; 2 stages = 64K smem -> 2 CTAs/SM.
// ---------------------------------------------------------------------------
#define GBM 128
#define GBN 128
#define GKC 64
#define GNIT (D / GKC)  // 16
#define STAGE_B 32768
#define GEMM_SMEM (2 * STAGE_B)

#define GEMM_F16_MAINLOOP(A, B, bm, bn, acc)                                  \
  extern __shared__ char sm_raw[];                                            \
  const uint32_t sbase = smem_u32(sm_raw);                                    \
  const int tid = threadIdx.x;                                                \
  const int wid = tid >> 5, lane = tid & 31;                                  \
  const int wm = (wid >> 2) * 64;                                             \
  const int wn = (wid & 3) * 32;                                              \
  float acc[4][4][4];                                                         \
  _Pragma("unroll") for (int mi = 0; mi < 4; mi++)                            \
      _Pragma("unroll") for (int ni = 0; ni < 4; ni++)                        \
      _Pragma("unroll") for (int j = 0; j < 4; j++) acc[mi][ni][j] = 0.f;     \
  auto load_stage = [&](int c) {                                              \
    const int kc = c * GKC;                                                   \
    const uint32_t buf = sbase + (c & 1) * STAGE_B;                           \
    _Pragma("unroll") for (int i = 0; i < 4; i++) {                           \
      int gid = tid + i * 256;                                                \
      int row = gid >> 3, g = gid & 7;                                        \
      uint32_t ph = (uint32_t)(row * 128 + ((g ^ (row & 7)) << 4));           \
      CP_ASYNC16(buf + ph,                                                    \
                 (const char*)(A + (size_t)(bm + row) * D + kc + g * 8));     \
      CP_ASYNC16(buf + 16384 + ph,                                            \
                 (const char*)(B + (size_t)(bn + row) * D + kc + g * 8));     \
    }                                                                         \
  };                                                                          \
  load_stage(0);                                                              \
  CP_COMMIT();                                                                \
  const int arow = ((lane >> 3) & 1) * 8 + (lane & 7);                        \
  const int asel = lane >> 4;                                                 \
  const int brow = lane & 7;                                                  \
  const int bsel = (lane >> 3) & 1;                                           \
  for (int c = 0; c < GNIT; c++) {                                            \
    if (c + 1 < GNIT) {                                                       \
      load_stage(c + 1);                                                      \
      CP_COMMIT();                                                            \
      CP_WAIT(1);                                                             \
    } else {                                                                  \
      CP_WAIT(0);                                                             \
    }                                                                         \
    __syncthreads();                                                          \
    const uint32_t Ah = sbase + (c & 1) * STAGE_B;                            \
    const uint32_t Bh = Ah + 16384;                                           \
    _Pragma("unroll") for (int ks = 0; ks < 4; ks++) {                        \
      uint32_t ah[4][4], bh[4][2];                                            \
      const int ag = 2 * ks + asel;                                           \
      const int bg = 2 * ks + bsel;                                           \
      _Pragma("unroll") for (int mi = 0; mi < 4; mi++) {                      \
        int row = wm + mi * 16 + arow;                                        \
        uint32_t off = (uint32_t)(row * 128 + ((ag ^ (row & 7)) << 4));       \
        LDSM4(ah[mi], Ah + off);                                              \
      }                                                                       \
      _Pragma("unroll") for (int ni = 0; ni < 4; ni++) {                      \
        int row = wn + ni * 8 + brow;                                         \
        uint32_t off = (uint32_t)(row * 128 + ((bg ^ (row & 7)) << 4));       \
        LDSM2(bh[ni], Bh + off);                                              \
      }                                                                       \
      _Pragma("unroll") for (int mi = 0; mi < 4; mi++)                        \
          _Pragma("unroll") for (int ni = 0; ni < 4; ni++) {                  \
        MMAH16816(acc[mi][ni], ah[mi], bh[ni]);                               \
      }                                                                       \
    }                                                                         \
    __syncthreads();                                                          \
  }

// QKV fused: z selects weight/output; epilogue -> fp16 (scaled)
__global__ __launch_bounds__(256, 2) void gemm_qkv_kernel(
    const unsigned short* __restrict__ A, const unsigned short* __restrict__ W,
    unsigned short* __restrict__ Qf, unsigned short* __restrict__ Kf,
    unsigned short* __restrict__ Vf) {
  const int z = blockIdx.z;
  const unsigned short* B = W + (size_t)z * D * D;
  unsigned short* out = (z == 0) ? Qf : (z == 1) ? Kf : Vf;
  const float alpha = (z == 0) ? QSCALE : 1.0f;
  const int bm = blockIdx.y * GBM, bn = blockIdx.x * GBN;

  GEMM_F16_MAINLOOP(A, B, bm, bn, acc)

  const int r0 = lane >> 2, c0 = (lane & 3) * 2;
#pragma unroll
  for (int mi = 0; mi < 4; mi++) {
#pragma unroll
    for (int ni = 0; ni < 4; ni++) {
      int col = bn + wn + ni * 8 + c0;
      int row = bm + wm + mi * 16 + r0;
      uint32_t p0, p1;
      PACK_F16X2(p0, acc[mi][ni][1] * alpha, acc[mi][ni][0] * alpha);
      PACK_F16X2(p1, acc[mi][ni][3] * alpha, acc[mi][ni][2] * alpha);
      *(uint32_t*)&out[(size_t)row * D + col] = p0;
      *(uint32_t*)&out[(size_t)(row + 8) * D + col] = p1;
    }
  }
}

// Final projection: fp32 + bias epilogue
__global__ __launch_bounds__(256, 2) void gemm_out_kernel(
    const unsigned short* __restrict__ A, const unsigned short* __restrict__ B,
    const float* __restrict__ bias, float* __restrict__ C) {
  const int bm = blockIdx.y * GBM, bn = blockIdx.x * GBN;

  GEMM_F16_MAINLOOP(A, B, bm, bn, acc)

  const int r0 = lane >> 2, c0 = (lane & 3) * 2;
#pragma unroll
  for (int mi = 0; mi < 4; mi++) {
#pragma unroll
    for (int ni = 0; ni < 4; ni++) {
      int col = bn + wn + ni * 8 + c0;
      float b0 = bias[col], b1 = bias[col + 1];
      int row = bm + wm + mi * 16 + r0;
      float2 v0 = make_float2(acc[mi][ni][0] + b0, acc[mi][ni][1] + b1);
      float2 v1 = make_float2(acc[mi][ni][2] + b0, acc[mi][ni][3] + b1);
      *(float2*)&C[(size_t)row * D + col] = v0;
      *(float2*)&C[(size_t)(row + 8) * D + col] = v1;
    }
  }
}

// ---------------------------------------------------------------------------
// Flash attention: fp16 single-product mma, fixed-max exp2 softmax,
// fp16 multiplier mask applied post-exp via HMUL2, row sums via ones-MMA.
// CTA = (128-q tile, head, batch); 8 warps x 16 q rows.
// Smem: Q 16K + 2 stages x (K 16K + V 16K + M 32K) = 144K.
// ---------------------------------------------------------------------------
#define ATTN_STAGE 65536
#define ATTN_SMEM (16384 + 2 * ATTN_STAGE)  // 147456

__global__ __launch_bounds__(256, 1) void attn_mma_kernel(
    const unsigned short* __restrict__ Qf, const unsigned short* __restrict__ Kf,
    const unsigned short* __restrict__ Vf, const unsigned short* __restrict__ Mf,
    unsigned short* __restrict__ Of) {
  extern __shared__ char sm_raw[];
  const uint32_t sb = smem_u32(sm_raw);
  const uint32_t sQ = sb, sKV = sb + 16384;

  const int tid = threadIdx.x;
  const int wid = tid >> 5, lane = tid & 31;
  const int qw = wid * 16;
  const int q0 = blockIdx.x * 128;
  const int h = blockIdx.y;
  const int bb = blockIdx.z;
  const size_t rowbase = (size_t)bb * NSEQ;
  const int colbase = h * HC;

  // ---- Q tile ----
  {
    const unsigned short* gq = Qf + (rowbase + q0) * D + colbase;
#pragma unroll
    for (int i = 0; i < 4; i++) {
      int idx = tid + 256 * i;
      int row = idx >> 3, g = idx & 7;
      uint32_t sw = (uint32_t)(row * 128 + ((g ^ (row & 7)) << 4));
      CP_ASYNC16(sQ + sw, (const char*)(gq + (size_t)row * D + g * 8));
    }
    CP_COMMIT();
  }

  // stage layout: K at +0 (16K), V at +16384 (16K), M at +32768 (32K)
  auto load_kv = [&](int c) {
    const int kb = c * 128;
    const uint32_t buf = sKV + (c & 1) * ATTN_STAGE;
#pragma unroll
    for (int i = 0; i < 4; i++) {
      int idx = tid + 256 * i;
      int row = idx >> 3, g = idx & 7;
      uint32_t sw = (uint32_t)(row * 128 + ((g ^ (row & 7)) << 4));
      size_t goff = (rowbase + kb + row) * D + colbase + g * 8;
      CP_ASYNC16(buf + sw, (const char*)(Kf + goff));
      CP_ASYNC16(buf + 16384 + sw, (const char*)(Vf + goff));
    }
    const unsigned short* gm = Mf + (rowbase + q0) * NSEQ + kb;
#pragma unroll
    for (int i = 0; i < 8; i++) {
      int idx = tid + 256 * i;
      int row = idx >> 4, gg = idx & 15;
      uint32_t sw = (uint32_t)(row * 256 + ((gg ^ (row & 7)) << 4));
      CP_ASYNC16(buf + 32768 + sw,
                 (const char*)(gm + (size_t)row * NSEQ + gg * 8));
    }
  };

  load_kv(0);
  CP_COMMIT();
  CP_WAIT(1);  // Q done
  __syncthreads();

  // ---- Q fragments ----
  const int arow = ((lane >> 3) & 1) * 8 + (lane & 7);
  const int asel = lane >> 4;
  uint32_t qf[4][4];
#pragma unroll
  for (int ks = 0; ks < 4; ks++) {
    int row = qw + arow;
    int g = 2 * ks + asel;
    uint32_t off = (uint32_t)(row * 128 + ((g ^ (row & 7)) << 4));
    LDSM4(qf[ks], sQ + off);
  }

  float o[8][4];
#pragma unroll
  for (int cn = 0; cn < 8; cn++)
#pragma unroll
    for (int j = 0; j < 4; j++) o[cn][j] = 0.f;
  float osum[4] = {0.f, 0.f, 0.f, 0.f};

  const int l7 = lane & 7;
  const int kmat = lane >> 3;
  const int tig = lane & 3;
  const int grp = lane >> 2;

  const uint32_t kbase0 = (uint32_t)(l7 * 128 + ((kmat ^ l7) << 4));
  const uint32_t kbase1 = (uint32_t)(l7 * 128 + (((4 + kmat) ^ l7) << 4));
  const uint32_t vrowoff = (uint32_t)((l7 + 8 * ((lane >> 3) & 1)) * 128);
  const int vgsel = lane >> 4;
  const int mrow = qw + arow;
  const uint32_t mbase = (uint32_t)(mrow * 256);
  const int mr7 = mrow & 7;
  const uint32_t ones2[2] = {0x3C003C00u, 0x3C003C00u};

  for (int c = 0; c < 16; c++) {
    if (c + 1 < 16) {
      load_kv(c + 1);
      CP_COMMIT();
      CP_WAIT(1);
    } else {
      CP_WAIT(0);
    }
    __syncthreads();
    const uint32_t bufK = sKV + (c & 1) * ATTN_STAGE;
    const uint32_t bufV = bufK + 16384;
    const uint32_t bufM = bufK + 32768;

    // ---- S = Q K^T ----
    float s[16][4];
#pragma unroll
    for (int nk = 0; nk < 16; nk++) {
#pragma unroll
      for (int j = 0; j < 4; j++) s[nk][j] = 0.f;
      uint32_t ka[4], kb2[4];
      LDSM4(ka, bufK + kbase0 + nk * 1024);
      LDSM4(kb2, bufK + kbase1 + nk * 1024);
      MMAH16816(s[nk], qf[0], (&ka[0]));
      MMAH16816(s[nk], qf[1], (&ka[2]));
      MMAH16816(s[nk], qf[2], (&kb2[0]));
      MMAH16816(s[nk], qf[3], (&kb2[2]));
    }

    // ---- exp2 (log2 domain, fixed max 0) ----
#pragma unroll
    for (int nk = 0; nk < 16; nk++) {
      EX2(s[nk][0], s[nk][0]);
      EX2(s[nk][1], s[nk][1]);
      EX2(s[nk][2], s[nk][2]);
      EX2(s[nk][3], s[nk][3]);
    }

    // ---- P = exp * mask;  rowsum via ones-MMA;  O += P V ----
#pragma unroll
    for (int g = 0; g < 8; g++) {
      uint32_t pa[4], ma[4];
      PACK_F16X2(pa[0], s[2 * g][1], s[2 * g][0]);
      PACK_F16X2(pa[1], s[2 * g][3], s[2 * g][2]);
      PACK_F16X2(pa[2], s[2 * g + 1][1], s[2 * g + 1][0]);
      PACK_F16X2(pa[3], s[2 * g + 1][3], s[2 * g + 1][2]);
      LDSM4(ma, bufM + mbase + (uint32_t)(((2 * g + asel) ^ mr7) << 4));
      HMUL2(pa[0], pa[0], ma[0]);
      HMUL2(pa[1], pa[1], ma[1]);
      HMUL2(pa[2], pa[2], ma[2]);
      HMUL2(pa[3], pa[3], ma[3]);
      MMAH16816(osum, pa, ones2);
      const uint32_t vrow_base = bufV + (uint32_t)(g * 2048) + vrowoff;
#pragma unroll
      for (int cnp = 0; cnp < 4; cnp++) {
        int gc = 2 * cnp + vgsel;
        uint32_t off = (uint32_t)((gc ^ l7) << 4);
        uint32_t vf4[4];
        LDSM4T(vf4, vrow_base + off);
        MMAH16816(o[2 * cnp], pa, (&vf4[0]));
        MMAH16816(o[2 * cnp + 1], pa, (&vf4[2]));
      }
    }
    __syncthreads();
  }

  // ---- epilogue: normalize by MMA row sums, write fp16 O ----
  float invA = 1.f / osum[0], invB = 1.f / osum[2];
  size_t rowA = rowbase + q0 + qw + grp;
#pragma unroll
  for (int cn = 0; cn < 8; cn++) {
    int col = colbase + 8 * cn + 2 * tig;
    uint32_t p0, p1;
    PACK_F16X2(p0, o[cn][1] * invA, o[cn][0] * invA);
    PACK_F16X2(p1, o[cn][3] * invB, o[cn][2] * invB);
    *(uint32_t*)&Of[rowA * D + col] = p0;
    *(uint32_t*)&Of[(rowA + 8) * D + col] = p1;
  }
}

// ---------------------------------------------------------------------------
extern "C" void kernel_launch(void* const* d_in, const int* in_sizes, int n_in,
                              void* d_out, int out_size) {
  const float* x = (const float*)d_in[0];
  const int* mask = (const int*)d_in[1];
  const float* Wq = (const float*)d_in[2];
  const float* Wk = (const float*)d_in[3];
  const float* Wv = (const float*)d_in[4];
  const float* Wp = (const float*)d_in[5];
  const float* bp = (const float*)d_in[6];
  float* out = (float*)d_out;

  unsigned short *pxf, *pqf, *pkf, *pvf, *pof, *pwtf, *pmf;
  cudaGetSymbolAddress((void**)&pxf, g_xf);
  cudaGetSymbolAddress((void**)&pqf, g_qf);
  cudaGetSymbolAddress((void**)&pkf, g_kf);
  cudaGetSymbolAddress((void**)&pvf, g_vf);
  cudaGetSymbolAddress((void**)&pof, g_of);
  cudaGetSymbolAddress((void**)&pwtf, g_wtf);
  cudaGetSymbolAddress((void**)&pmf, g_mf);

  cudaFuncSetAttribute(gemm_qkv_kernel,
                       cudaFuncAttributeMaxDynamicSharedMemorySize, GEMM_SMEM);
  cudaFuncSetAttribute(gemm_out_kernel,
                       cudaFuncAttributeMaxDynamicSharedMemorySize, GEMM_SMEM);
  cudaFuncSetAttribute(attn_mma_kernel,
                       cudaFuncAttributeMaxDynamicSharedMemorySize, ATTN_SMEM);

  dim3 tb(32, 8), tg(32, 32, 4);
  transpose_f16_kernel<<<tg, tb>>>(Wq, Wk, Wv, Wp, pwtf);

  cvt_f16_kernel<<<(M_TOTAL * D / 4 + 255) / 256, 256>>>(x, pxf,
                                                         M_TOTAL * D / 4);
  maskf16_kernel<<<(NB * NSEQ * NSEQ / 8) / 256, 256>>>(mask, pmf);

  dim3 gqkv(D / GBN, M_TOTAL / GBM, 3);  // (8, 32, 3)
  gemm_qkv_kernel<<<gqkv, 256, GEMM_SMEM>>>(pxf, pwtf, pqf, pkf, pvf);

  attn_mma_kernel<<<dim3(NSEQ / 128, NH, NB), 256, ATTN_SMEM>>>(
      pqf, pkf, pvf, pmf, pof);

  dim3 gg(D / GBN, M_TOTAL / GBM);  // (8, 32)
  gemm_out_kernel<<<gg, 256, GEMM_SMEM>>>(pof, pwtf + 3 * (size_t)D * D, bp,
                                          out);
}